// round 12
// baseline (speedup 1.0000x reference)
#include <cuda_runtime.h>
#include <cuda_fp16.h>
#include <cstdint>

#define TT 8
#define NSUB 20000
#define MSUB 5000
#define HD 128
#define NNZG 200000
#define NNZE 100000
#define ITEM_NUM 40000
#define USER_NUM 10000
#define ITEM_DY_NUM 60000

#define LDA 264
#define LDB 136
#define B_BYTES (256 * LDB * 2)      // 69632
#define GB_BYTES (128 * LDB * 2)     // 34816
#define GA_BYTES (64 * LDA * 2)      // 33792
#define HA_BYTES (128 * LDA * 2)     // 67584
#define HG_SMEM (B_BYTES + 2 * HA_BYTES)            // 204800
#define FA0_OFF (GB_BYTES + B_BYTES)                // 104448
#define FU_SMEM (FA0_OFF + 2 * GA_BYTES)            // 172032
#define GRIDX 19
#define GTILES ((NSUB + 63) / 64)    // 313
#define HTILES ((NSUB + 127) / 128)  // 157

// ---------------- scratch ---------------------------------------------------
__device__ __align__(16) __half g_Yh[(long)TT * NSUB * HD];
__device__ __align__(16) __half g_Eh[(long)TT * NSUB * HD];
__device__ __align__(16) __half g_Wt[24 * 256 * LDB];
__device__ __align__(16) __half g_items[(long)ITEM_NUM * 256];
__device__ __align__(16) __half g_dys[(long)ITEM_DY_NUM * 256];
__device__ __align__(16) __half g_Xs[(long)TT * NSUB * 256];

__device__ int   g_cnt[TT * NSUB];
__device__ int   g_ptrA[TT * (NSUB + 1)];
__device__ int   g_posA[TT * NSUB];
__device__ int   g_ci[TT * NNZG];
__device__ float g_cvv[TT * NNZG];

__device__ int   e_cnt[TT * MSUB];
__device__ int   e_ptrA[TT * (MSUB + 1)];
__device__ int   e_posA[TT * MSUB];
__device__ int   e_ci[TT * NNZE];
__device__ float e_cvv[TT * NNZE];

// ---------------- helpers ---------------------------------------------------
__device__ __forceinline__ uint32_t smem_u32(const void* p) {
    uint32_t a;
    asm("{ .reg .u64 t; cvta.to.shared.u64 t, %1; cvt.u32.u64 %0, t; }" : "=r"(a) : "l"(p));
    return a;
}
__device__ __forceinline__ void ldsm4(uint32_t* r, uint32_t addr) {
    asm volatile("ldmatrix.sync.aligned.m8n8.x4.shared.b16 {%0,%1,%2,%3}, [%4];"
                 : "=r"(r[0]), "=r"(r[1]), "=r"(r[2]), "=r"(r[3]) : "r"(addr));
}
__device__ __forceinline__ void ldsm4t(uint32_t* r, uint32_t addr) {
    asm volatile("ldmatrix.sync.aligned.m8n8.x4.trans.shared.b16 {%0,%1,%2,%3}, [%4];"
                 : "=r"(r[0]), "=r"(r[1]), "=r"(r[2]), "=r"(r[3]) : "r"(addr));
}
__device__ __forceinline__ void mma16816(float* c, const uint32_t* a, const uint32_t* b) {
    asm volatile("mma.sync.aligned.m16n8k16.row.col.f32.f16.f16.f32 "
                 "{%0,%1,%2,%3}, {%4,%5,%6,%7}, {%8,%9}, {%0,%1,%2,%3};"
                 : "+f"(c[0]), "+f"(c[1]), "+f"(c[2]), "+f"(c[3])
                 : "r"(a[0]), "r"(a[1]), "r"(a[2]), "r"(a[3]), "r"(b[0]), "r"(b[1]));
}
__device__ __forceinline__ void split4h(float4 v, uint2& hi, uint2& lo) {
    __half h[4], l[4];
    float x[4] = {v.x, v.y, v.z, v.w};
#pragma unroll
    for (int j = 0; j < 4; j++) {
        h[j] = __float2half(x[j]);
        l[j] = __float2half(x[j] - __half2float(h[j]));
    }
    hi = *(uint2*)h; lo = *(uint2*)l;
}
#define CP16(dst, src) asm volatile("cp.async.cg.shared.global [%0], [%1], 16;" :: "r"(dst), "l"(src))
#define CP_COMMIT()    asm volatile("cp.async.commit_group;" ::: "memory")
#define CP_WAIT1()     asm volatile("cp.async.wait_group 1;" ::: "memory")
#define CP_WAIT0()     asm volatile("cp.async.wait_group 0;" ::: "memory")

// ---------------- CSR build --------------------------------------------------
__global__ void zero_cnt_kernel() {
    int i = blockIdx.x * blockDim.x + threadIdx.x;
    if (i < TT * NSUB) g_cnt[i] = 0;
    if (i < TT * MSUB) e_cnt[i] = 0;
}

__global__ void hist_kernel(const int* __restrict__ rows, int* __restrict__ cnt,
                            int nnz, int nrows) {
    int i = blockIdx.x * blockDim.x + threadIdx.x;
    if (i >= TT * nnz) return;
    int t = i / nnz;
    atomicAdd(&cnt[t * nrows + rows[i]], 1);
}

__global__ __launch_bounds__(1024) void scan2_kernel() {
    int b = blockIdx.x;
    const int* cnt; int* ptr; int* pos; int n;
    if (b < TT) { cnt = g_cnt + b * NSUB; ptr = g_ptrA + b * (NSUB + 1); pos = g_posA + b * NSUB; n = NSUB; }
    else { int t = b - TT; cnt = e_cnt + t * MSUB; ptr = e_ptrA + t * (MSUB + 1); pos = e_posA + t * MSUB; n = MSUB; }
    __shared__ int wsum[32];
    __shared__ int s_carry;
    int tid = threadIdx.x, lane = tid & 31, wp = tid >> 5;
    if (tid == 0) s_carry = 0;
    __syncthreads();
    for (int base = 0; base < n; base += 8192) {
        int i0 = base + tid * 8;
        int v[8]; int sum = 0;
#pragma unroll
        for (int j = 0; j < 8; j++) { v[j] = (i0 + j < n) ? cnt[i0 + j] : 0; sum += v[j]; }
        int s = sum;
#pragma unroll
        for (int o = 1; o < 32; o <<= 1) { int u = __shfl_up_sync(0xffffffffu, s, o); if (lane >= o) s += u; }
        if (lane == 31) wsum[wp] = s;
        __syncthreads();
        if (wp == 0) {
            int t2 = wsum[lane];
            int ss = t2;
#pragma unroll
            for (int o = 1; o < 32; o <<= 1) { int u = __shfl_up_sync(0xffffffffu, ss, o); if (lane >= o) ss += u; }
            wsum[lane] = ss - t2;
        }
        __syncthreads();
        int run = s_carry + wsum[wp] + s - sum;
#pragma unroll
        for (int j = 0; j < 8; j++) {
            if (i0 + j < n) { ptr[i0 + j] = run; pos[i0 + j] = run; }
            run += v[j];
        }
        __syncthreads();
        if (tid == 1023) s_carry = run;
        __syncthreads();
    }
    if (tid == 0) ptr[n] = s_carry;
}

__global__ void scatter_kernel(const int* __restrict__ rows, const int* __restrict__ cols,
                               const float* __restrict__ vals, int* __restrict__ pos,
                               int* __restrict__ ci, float* __restrict__ cv,
                               int nnz, int nrows) {
    int i = blockIdx.x * blockDim.x + threadIdx.x;
    if (i >= TT * nnz) return;
    int t = i / nnz;
    int r = rows[i];
    int p = atomicAdd(&pos[t * nrows + r], 1);
    ci[(long)t * nnz + p] = cols[i];
    cv[(long)t * nnz + p] = vals[i];
}

// ---------------- SpMM: fp16 row gather -------------------------------------
__global__ void spmm_h(const int* __restrict__ ptr, const int* __restrict__ ci,
                       const float* __restrict__ cv,
                       const __half* __restrict__ xh, long xts,
                       float* __restrict__ yb, long yts,
                       __half* __restrict__ ys_split, __half* __restrict__ ys_hi,
                       const float* __restrict__ bias, int bstride,
                       int rows_per_t, int nnz, int do_relu) {
    int w = (blockIdx.x * blockDim.x + threadIdx.x) >> 5;
    int lane = threadIdx.x & 31;
    if (w >= TT * rows_per_t) return;
    int t = w / rows_per_t;
    int r = w - t * rows_per_t;
    const int* pp = ptr + t * (rows_per_t + 1);
    int jb = pp[r], je = pp[r + 1];
    const uint2* x2 = (const uint2*)(xh + (long)t * xts);
    const int*   cit = ci + (long)t * nnz;
    const float* cvt = cv + (long)t * nnz;
    float4 acc = make_float4(0.f, 0.f, 0.f, 0.f);
    float vsum = 0.f;
    int j = jb;
    for (; j + 4 <= je; j += 4) {
        int c0 = __ldg(cit + j),     c1 = __ldg(cit + j + 1);
        int c2 = __ldg(cit + j + 2), c3 = __ldg(cit + j + 3);
        float v0 = __ldg(cvt + j),     v1 = __ldg(cvt + j + 1);
        float v2 = __ldg(cvt + j + 2), v3 = __ldg(cvt + j + 3);
        uint2 u0 = x2[(long)c0 * 32 + lane];
        uint2 u1 = x2[(long)c1 * 32 + lane];
        uint2 u2 = x2[(long)c2 * 32 + lane];
        uint2 u3 = x2[(long)c3 * 32 + lane];
        vsum += v0 + v1 + v2 + v3;
        float2 a0 = __half22float2(*(__half2*)&u0.x), b0 = __half22float2(*(__half2*)&u0.y);
        float2 a1 = __half22float2(*(__half2*)&u1.x), b1 = __half22float2(*(__half2*)&u1.y);
        float2 a2 = __half22float2(*(__half2*)&u2.x), b2 = __half22float2(*(__half2*)&u2.y);
        float2 a3 = __half22float2(*(__half2*)&u3.x), b3 = __half22float2(*(__half2*)&u3.y);
        acc.x += v0 * a0.x + v1 * a1.x + v2 * a2.x + v3 * a3.x;
        acc.y += v0 * a0.y + v1 * a1.y + v2 * a2.y + v3 * a3.y;
        acc.z += v0 * b0.x + v1 * b1.x + v2 * b2.x + v3 * b3.x;
        acc.w += v0 * b0.y + v1 * b1.y + v2 * b2.y + v3 * b3.y;
    }
    for (; j < je; j++) {
        int   c0 = __ldg(cit + j);
        float v0 = __ldg(cvt + j);
        uint2 u0 = x2[(long)c0 * 32 + lane];
        float2 a0 = __half22float2(*(__half2*)&u0.x), b0 = __half22float2(*(__half2*)&u0.y);
        vsum += v0;
        acc.x += v0 * a0.x; acc.y += v0 * a0.y;
        acc.z += v0 * b0.x; acc.w += v0 * b0.y;
    }
    if (bias) {
        float4 bv = ((const float4*)(bias + (long)t * bstride))[lane];
        acc.x += vsum * bv.x; acc.y += vsum * bv.y; acc.z += vsum * bv.z; acc.w += vsum * bv.w;
    }
    if (do_relu) {
        acc.x = fmaxf(acc.x, 0.f); acc.y = fmaxf(acc.y, 0.f);
        acc.z = fmaxf(acc.z, 0.f); acc.w = fmaxf(acc.w, 0.f);
    }
    if (ys_split) {
        uint2 hi, lo; split4h(acc, hi, lo);
        __half* yr = ys_split + ((long)t * rows_per_t + r) * 256;
        *(uint2*)(yr + lane * 4) = hi;
        *(uint2*)(yr + 128 + lane * 4) = lo;
    }
    if (ys_hi) {
        uint2 hp;
        *(__half2*)&hp.x = __floats2half2_rn(acc.x, acc.y);
        *(__half2*)&hp.y = __floats2half2_rn(acc.z, acc.w);
        ((uint2*)(ys_hi + ((long)t * rows_per_t + r) * HD))[lane] = hp;
    }
    if (yb)
        ((float4*)(yb + (long)t * yts))[r * 32 + lane] = acc;
}

// ---------------- prep_w ----------------------------------------------------
__global__ __launch_bounds__(256) void prep_w(const float* __restrict__ Wg,
                                              const float* __restrict__ Wh) {
    int b = blockIdx.x, t = b / 3, s = b % 3;
    int tid = threadIdx.x;
    const float* W = (s == 0) ? Wg + (long)t * 16384 : Wh + ((long)t * 2 + (s - 1)) * 16384;
    __half* dst = g_Wt + (long)b * 256 * LDB;
    const float4* w4 = (const float4*)W;
    for (int i = tid; i < 4096; i += 256) {
        int k = i >> 5, c4 = (i & 31) * 4;
        uint2 hi, lo; split4h(w4[i], hi, lo);
        *(uint2*)(dst + k * LDB + c4) = hi;
        *(uint2*)(dst + (k + 128) * LDB + c4) = lo;
    }
}

// ---------------- prep_tables -----------------------------------------------
__global__ __launch_bounds__(256) void prep_tables(const float* __restrict__ ib,
                                                   const float* __restrict__ dt) {
    long i = (long)blockIdx.x * blockDim.x + threadIdx.x;
    const long NI = (long)ITEM_NUM * 32;
    const long ND = (long)ITEM_DY_NUM * 32;
    if (i < NI) {
        long row = i >> 5; int c4 = (int)(i & 31) * 4;
        uint2 hi, lo; split4h(((const float4*)ib)[i], hi, lo);
        *(uint2*)(g_items + row * 256 + c4) = hi;
        *(uint2*)(g_items + row * 256 + 128 + c4) = lo;
    } else if (i < NI + ND) {
        long j = i - NI;
        long row = j >> 5; int c4 = (int)(j & 31) * 4;
        uint2 hi, lo; split4h(((const float4*)dt)[j], hi, lo);
        *(uint2*)(g_dys + row * 256 + c4) = hi;
        *(uint2*)(g_dys + row * 256 + 128 + c4) = lo;
    }
}

// ---------------- fused gate + HGNN layer-0 GEMM, M=64 tiles ----------------
// smem: [Bg hi 34816][B1 hi+lo 69632][A0 33792][A1 33792]
// After the gate epilogue, X (split) overwrites A1 in-place; GEMM2 = X @ W1.
__global__ __launch_bounds__(512, 1) void gate_fused(
    const float* __restrict__ bg,
    const int* __restrict__ rev_i, const int* __restrict__ rev_lat) {
    extern __shared__ char sm[];
    uint32_t smbU = smem_u32(sm);
    int t = blockIdx.y;
    int tid = threadIdx.x, lane = tid & 31, wid = tid >> 5;
    int wm = wid & 1, wn = wid >> 1;   // 2 x 8 warps (M=64, N=128)

    uint32_t a0Base = smbU + FA0_OFF;
    uint32_t a1Base = a0Base + GA_BYTES;
    uint32_t b1Base = smbU + GB_BYTES;

    // fill one 64-row A region: which=0 -> items via rev_i, which=1 -> dys via rev_lat
    auto fillA = [&](int which, int tile) {
        int rbase = tile * 64;
        uint32_t aBase = which ? a1Base : a0Base;
        const __half* tab = which ? g_dys : g_items;
        const int* idx = which ? rev_lat : rev_i;
        for (int i = tid; i < 2048; i += 512) {
            int r = i >> 5, ch = i & 31;
            int row = rbase + r; if (row >= NSUB) row = NSUB - 1;
            int gidx = __ldg(idx + t * NSUB + row);
            CP16(aBase + r * 528 + ch * 16, (const char*)(tab + (long)gidx * 256) + ch * 16);
        }
    };

    {   // prologue: Bg (hi only), B1 (hi+lo), first A0/A1
        const char* bsrc = (const char*)(g_Wt + (long)(t * 3) * 256 * LDB);
        for (int q = tid; q < GB_BYTES / 16; q += 512)
            CP16(smbU + q * 16, bsrc + q * 16);
        const char* b1src = (const char*)(g_Wt + (long)(t * 3 + 1) * 256 * LDB);
        for (int q = tid; q < B_BYTES / 16; q += 512)
            CP16(b1Base + q * 16, b1src + q * 16);
        fillA(0, blockIdx.x);
        fillA(1, blockIdx.x);
        CP_COMMIT();
        CP_WAIT0();
        __syncthreads();
    }

    for (int i = blockIdx.x; i < GTILES; i += GRIDX) {
        int nxt = i + GRIDX;

        // ---- gate GEMMs: logits0 = A0h @ Bg, logits1 = A1h @ Bg ----
        float acc0[2][2][4], acc1[2][2][4];
#pragma unroll
        for (int mi = 0; mi < 2; mi++)
#pragma unroll
            for (int nj = 0; nj < 2; nj++)
#pragma unroll
                for (int q = 0; q < 4; q++) { acc0[mi][nj][q] = 0.f; acc1[mi][nj][q] = 0.f; }
#pragma unroll
        for (int ks = 0; ks < 8; ks++) {
            int k = ks * 16;
            uint32_t a0h[2][4], a1h[2][4], bb[4];
#pragma unroll
            for (int mi = 0; mi < 2; mi++) {
                uint32_t off = ((wm * 32 + mi * 16 + (lane & 15)) * LDA + k + (lane >> 4) * 8) * 2;
                ldsm4(a0h[mi], a0Base + off);
                ldsm4(a1h[mi], a1Base + off);
            }
            ldsm4t(bb, smbU + ((k + (lane & 15)) * LDB + wn * 16 + (lane >> 4) * 8) * 2);
#pragma unroll
            for (int mi = 0; mi < 2; mi++)
#pragma unroll
                for (int nj = 0; nj < 2; nj++) {
                    mma16816(acc0[mi][nj], a0h[mi], &bb[nj * 2]);
                    mma16816(acc1[mi][nj], a1h[mi], &bb[nj * 2]);
                }
        }
        __syncthreads();   // all gate reads of A0/A1 complete

        // ---- epilogue: X = x0*sig(p0+b) + x1*sig(p1+b); write split X into A1 ----
        {
            const __half* A0h = (const __half*)(sm + FA0_OFF);
            const __half* A1h = A0h + GA_BYTES / 2;
            __half* A1w = (__half*)(sm + FA0_OFF + GA_BYTES);
#pragma unroll
            for (int mi = 0; mi < 2; mi++)
#pragma unroll
                for (int nj = 0; nj < 2; nj++)
#pragma unroll
                    for (int h = 0; h < 2; h++) {
                        int r = wm * 32 + mi * 16 + (lane >> 2) + h * 8;
                        int col = wn * 16 + nj * 8 + (lane & 3) * 2;
                        float pa0 = acc0[mi][nj][h * 2], pa1 = acc0[mi][nj][h * 2 + 1];
                        float pb0 = acc1[mi][nj][h * 2], pb1 = acc1[mi][nj][h * 2 + 1];
                        __half2 h0 = *(const __half2*)(A0h + r * LDA + col);
                        __half2 l0 = *(const __half2*)(A0h + r * LDA + 128 + col);
                        __half2 h1 = *(const __half2*)(A1h + r * LDA + col);
                        __half2 l1 = *(const __half2*)(A1h + r * LDA + 128 + col);
                        float x00 = __half2float(h0.x) + __half2float(l0.x);
                        float x01 = __half2float(h0.y) + __half2float(l0.y);
                        float x10 = __half2float(h1.x) + __half2float(l1.x);
                        float x11 = __half2float(h1.y) + __half2float(l1.y);
                        float bv0 = __ldg(bg + t * HD + col), bv1 = __ldg(bg + t * HD + col + 1);
                        float s0a = __fdividef(1.f, 1.f + __expf(-(pa0 + bv0)));
                        float s0b = __fdividef(1.f, 1.f + __expf(-(pb0 + bv0)));
                        float s1a = __fdividef(1.f, 1.f + __expf(-(pa1 + bv1)));
                        float s1b = __fdividef(1.f, 1.f + __expf(-(pb1 + bv1)));
                        float ox = x00 * s0a + x10 * s0b;
                        float oy = x01 * s1a + x11 * s1b;
                        __half hx = __float2half(ox), hy = __float2half(oy);
                        __half lx = __float2half(ox - __half2float(hx));
                        __half ly = __float2half(oy - __half2float(hy));
                        __half2 hp, lp;
                        hp.x = hx; hp.y = hy; lp.x = lx; lp.y = ly;
                        *(__half2*)(A1w + r * LDA + col) = hp;
                        *(__half2*)(A1w + r * LDA + 128 + col) = lp;
                    }
        }
        __syncthreads();   // X fully materialized in A1

        // prefetch next tile's A0 (A0 is dead now) to overlap with GEMM2
        if (nxt < GTILES) { fillA(0, nxt); CP_COMMIT(); }

        // ---- GEMM2: Y = X @ W1 (3-term), X in A1 region ----
        float acc2[2][2][4];
#pragma unroll
        for (int mi = 0; mi < 2; mi++)
#pragma unroll
            for (int nj = 0; nj < 2; nj++)
#pragma unroll
                for (int q = 0; q < 4; q++) acc2[mi][nj][q] = 0.f;
#pragma unroll
        for (int ks = 0; ks < 8; ks++) {
            int k = ks * 16;
            uint32_t ah[2][4], al[2][4], bhh[4], bll[4];
#pragma unroll
            for (int mi = 0; mi < 2; mi++) {
                uint32_t off = ((wm * 32 + mi * 16 + (lane & 15)) * LDA + k + (lane >> 4) * 8) * 2;
                ldsm4(ah[mi], a1Base + off);
                ldsm4(al[mi], a1Base + off + 256);
            }
            uint32_t boff = ((k + (lane & 15)) * LDB + wn * 16 + (lane >> 4) * 8) * 2;
            ldsm4t(bhh, b1Base + boff);
            ldsm4t(bll, b1Base + boff + 128 * LDB * 2);
#pragma unroll
            for (int mi = 0; mi < 2; mi++)
#pragma unroll
                for (int nj = 0; nj < 2; nj++) {
                    mma16816(acc2[mi][nj], ah[mi], &bhh[nj * 2]);
                    mma16816(acc2[mi][nj], al[mi], &bhh[nj * 2]);
                    mma16816(acc2[mi][nj], ah[mi], &bll[nj * 2]);
                }
        }

        // write Y (fp16) to g_Yh
        {
            __half* Yt = g_Yh + (long)t * NSUB * HD;
            int rbase = i * 64;
#pragma unroll
            for (int mi = 0; mi < 2; mi++) {
                int r0 = rbase + wm * 32 + mi * 16 + (lane >> 2);
#pragma unroll
                for (int nj = 0; nj < 2; nj++) {
                    int col = wn * 16 + nj * 8 + (lane & 3) * 2;
                    if (r0 < NSUB)
                        *(__half2*)(Yt + (long)r0 * HD + col) = __floats2half2_rn(acc2[mi][nj][0], acc2[mi][nj][1]);
                    if (r0 + 8 < NSUB)
                        *(__half2*)(Yt + (long)(r0 + 8) * HD + col) = __floats2half2_rn(acc2[mi][nj][2], acc2[mi][nj][3]);
                }
            }
        }
        __syncthreads();   // GEMM2 reads of A1 done before refill

        if (nxt < GTILES) { fillA(1, nxt); CP_COMMIT(); }
        CP_WAIT0();
        __syncthreads();
    }
}

// ---------------- hgnn layer-1 GEMM (unchanged, M=128, double-buffered) -----
__global__ __launch_bounds__(512, 1) void hgnn_mm(int l) {
    extern __shared__ char sm[];
    uint32_t smbU = smem_u32(sm);
    int t = blockIdx.y;
    int tid = threadIdx.x, lane = tid & 31, wid = tid >> 5;
    int wm = wid & 3, wn = wid >> 2;

    {
        const char* bsrc = (const char*)(g_Wt + (long)(t * 3 + 1 + l) * 256 * LDB);
        for (int q = tid; q < B_BYTES / 16; q += 512)
            CP16(smbU + q * 16, bsrc + q * 16);
    }
    auto fillA = [&](int p, int tile) {
        int rbase = tile * 128;
        uint32_t aBase = smbU + B_BYTES + p * HA_BYTES;
        const __half* xs = g_Xs + (long)t * NSUB * 256;
        for (int i = tid; i < 4096; i += 512) {
            int r = i >> 5, ch = i & 31;
            int row = rbase + r; if (row >= NSUB) row = 0;
            CP16(aBase + r * 528 + ch * 16, (const char*)(xs + (long)row * 256) + ch * 16);
        }
    };

    int i0 = blockIdx.x;
    fillA(0, i0);
    CP_COMMIT();

    int buf = 0;
    for (int i = i0; i < HTILES; i += GRIDX) {
        int nxt = i + GRIDX;
        if (nxt < HTILES) fillA(buf ^ 1, nxt);
        CP_COMMIT();
        CP_WAIT1();
        __syncthreads();

        float acc[2][4][4];
#pragma unroll
        for (int mi = 0; mi < 2; mi++)
#pragma unroll
            for (int nj = 0; nj < 4; nj++)
#pragma unroll
                for (int q = 0; q < 4; q++) acc[mi][nj][q] = 0.f;

        uint32_t aBase = smbU + B_BYTES + buf * HA_BYTES;
#pragma unroll
        for (int ks = 0; ks < 8; ks++) {
            int k = ks * 16;
            uint32_t ah[2][4], al[2][4], bh[2][4], bl[2][4];
#pragma unroll
            for (int mi = 0; mi < 2; mi++) {
                uint32_t off = ((wm * 32 + mi * 16 + (lane & 15)) * LDA + k + (lane >> 4) * 8) * 2;
                ldsm4(ah[mi], aBase + off);
                ldsm4(al[mi], aBase + off + 256);
            }
#pragma unroll
            for (int p = 0; p < 2; p++) {
                uint32_t off = ((k + (lane & 15)) * LDB + wn * 32 + p * 16 + (lane >> 4) * 8) * 2;
                ldsm4t(bh[p], smbU + off);
                ldsm4t(bl[p], smbU + off + 128 * LDB * 2);
            }
#pragma unroll
            for (int mi = 0; mi < 2; mi++)
#pragma unroll
                for (int nj = 0; nj < 4; nj++) {
                    const uint32_t* bhf = &bh[nj >> 1][(nj & 1) * 2];
                    const uint32_t* blf = &bl[nj >> 1][(nj & 1) * 2];
                    mma16816(acc[mi][nj], ah[mi], bhf);
                    mma16816(acc[mi][nj], al[mi], bhf);
                    mma16816(acc[mi][nj], ah[mi], blf);
                }
        }

        __half* Yt = g_Yh + (long)t * NSUB * HD;
        int mbase = i * 128;
#pragma unroll
        for (int mi = 0; mi < 2; mi++) {
            int r0 = mbase + wm * 32 + mi * 16 + (lane >> 2);
#pragma unroll
            for (int nj = 0; nj < 4; nj++) {
                int col = wn * 32 + nj * 8 + (lane & 3) * 2;
                if (r0 < NSUB)
                    *(__half2*)(Yt + (long)r0 * HD + col) = __floats2half2_rn(acc[mi][nj][0], acc[mi][nj][1]);
                if (r0 + 8 < NSUB)
                    *(__half2*)(Yt + (long)(r0 + 8) * HD + col) = __floats2half2_rn(acc[mi][nj][2], acc[mi][nj][3]);
            }
        }
        __syncthreads();
        buf ^= 1;
    }
}

// ---------------- host ------------------------------------------------------
static void* sym_addr(const void* sym) { void* p = 0; cudaGetSymbolAddress(&p, sym); return p; }

extern "C" void kernel_launch(void* const* d_in, const int* in_sizes, int n_in,
                              void* d_out, int out_size) {
    const float* item_base = (const float*)d_in[0];
    const float* user_base = (const float*)d_in[1];
    const float* dy_tab    = (const float*)d_in[2];
    const float* Wg        = (const float*)d_in[3];
    const float* bg        = (const float*)d_in[4];
    const float* Wh        = (const float*)d_in[5];
    const float* bh        = (const float*)d_in[6];
    const float* gv        = (const float*)d_in[7];
    const float* ev        = (const float*)d_in[8];
    const int*   rev_i     = (const int*)d_in[9];
    const int*   rev_lat   = (const int*)d_in[10];
    const int*   grows     = (const int*)d_in[11];
    const int*   gcols     = (const int*)d_in[12];
    const int*   erows     = (const int*)d_in[13];
    const int*   ecols     = (const int*)d_in[14];
    float* out = (float*)d_out;

    static cudaStream_t s2 = 0;
    static cudaEvent_t evF = 0, evJ = 0;
    if (!s2) {
        cudaStreamCreateWithFlags(&s2, cudaStreamNonBlocking);
        cudaEventCreateWithFlags(&evF, cudaEventDisableTiming);
        cudaEventCreateWithFlags(&evJ, cudaEventDisableTiming);
        cudaFuncSetAttribute(hgnn_mm,    cudaFuncAttributeMaxDynamicSharedMemorySize, HG_SMEM);
        cudaFuncSetAttribute(gate_fused, cudaFuncAttributeMaxDynamicSharedMemorySize, FU_SMEM);
    }

    int* d_gptr = (int*)sym_addr(g_ptrA);
    int* d_gpos = (int*)sym_addr(g_posA);
    int* d_gci  = (int*)sym_addr(g_ci);
    float* d_gcv = (float*)sym_addr(g_cvv);
    int* d_eptr = (int*)sym_addr(e_ptrA);
    int* d_epos = (int*)sym_addr(e_posA);
    int* d_eci  = (int*)sym_addr(e_ci);
    float* d_ecv = (float*)sym_addr(e_cvv);
    __half* d_Yh = (__half*)sym_addr(g_Yh);
    __half* d_Eh = (__half*)sym_addr(g_Eh);
    __half* d_Xs = (__half*)sym_addr(g_Xs);
    int* d_gcnt = (int*)sym_addr(g_cnt);
    int* d_ecnt = (int*)sym_addr(e_cnt);

    dim3 tgrid(GRIDX, TT);

    // fork: CSR build on s2 overlaps the dense prologue
    cudaEventRecord(evF, 0);
    cudaStreamWaitEvent(s2, evF, 0);

    cudaMemcpyAsync(out, user_base, (size_t)USER_NUM * HD * sizeof(float),
                    cudaMemcpyDeviceToDevice, 0);                                   // 0
    cudaMemcpyAsync(out + (size_t)(USER_NUM + TT * MSUB) * HD, item_base,
                    (size_t)ITEM_NUM * HD * sizeof(float), cudaMemcpyDeviceToDevice, 0); // 1
    prep_w<<<24, 256>>>(Wg, Wh);                                                    // 2
    prep_tables<<<((ITEM_NUM + ITEM_DY_NUM) * 32 + 255) / 256, 256>>>(item_base, dy_tab); // 3
    zero_cnt_kernel<<<(TT * NSUB + 255) / 256, 256, 0, s2>>>();                     // 4
    gate_fused<<<tgrid, 512, FU_SMEM>>>(bg, rev_i, rev_lat);                        // 5 <- profiled
    hist_kernel<<<(TT * NNZG + 255) / 256, 256, 0, s2>>>(grows, d_gcnt, NNZG, NSUB);
    hist_kernel<<<(TT * NNZE + 255) / 256, 256, 0, s2>>>(erows, d_ecnt, NNZE, MSUB);
    scan2_kernel<<<16, 1024, 0, s2>>>();
    scatter_kernel<<<(TT * NNZG + 255) / 256, 256, 0, s2>>>(grows, gcols, gv, d_gpos, d_gci, d_gcv, NNZG, NSUB);
    scatter_kernel<<<(TT * NNZE + 255) / 256, 256, 0, s2>>>(erows, ecols, ev, d_epos, d_eci, d_ecv, NNZE, MSUB);
    cudaEventRecord(evJ, s2);

    // join: SpMM needs CSR (gate_fused already produced g_Yh on stream 0)
    cudaStreamWaitEvent(0, evJ, 0);

    float* out_item = out + (size_t)(USER_NUM + TT * MSUB + ITEM_NUM) * HD;
    float* out_user = out + (size_t)USER_NUM * HD;

    // layer 0 SpMM: gather g_Yh (fp16), write split g_Xs
    spmm_h<<<(TT * NSUB * 32) / 256, 256>>>(d_gptr, d_gci, d_gcv,
        d_Yh, (long)NSUB * HD, (float*)nullptr, 0, d_Xs, (__half*)nullptr,
        bh + 0 * HD, 2 * HD, NSUB, NNZG, 1);
    hgnn_mm<<<tgrid, 512, HG_SMEM>>>(1);
    // layer 1 SpMM: gather g_Yh, write fp32 out_item + fp16 image g_Eh
    spmm_h<<<(TT * NSUB * 32) / 256, 256>>>(d_gptr, d_gci, d_gcv,
        d_Yh, (long)NSUB * HD, out_item, (long)NSUB * HD, (__half*)nullptr, d_Eh,
        bh + 1 * HD, 2 * HD, NSUB, NNZG, 1);
    // edge aggregation: gather g_Eh (fp16), write fp32 user area
    spmm_h<<<(TT * MSUB * 32) / 256, 256>>>(d_eptr, d_eci, d_ecv,
        d_Eh, (long)NSUB * HD, out_user, (long)MSUB * HD, (__half*)nullptr, (__half*)nullptr,
        (const float*)nullptr, 0, MSUB, NNZE, 0);
}

// round 13
// speedup vs baseline: 1.0256x; 1.0256x over previous
#include <cuda_runtime.h>
#include <cuda_fp16.h>
#include <cstdint>

#define TT 8
#define NSUB 20000
#define MSUB 5000
#define HD 128
#define NNZG 200000
#define NNZE 100000
#define ITEM_NUM 40000
#define USER_NUM 10000
#define ITEM_DY_NUM 60000

#define LDA 264
#define LDB 136
#define B_BYTES (256 * LDB * 2)
#define GB_BYTES (128 * LDB * 2)
#define GA_BYTES (64 * LDA * 2)
#define HA_BYTES (128 * LDA * 2)
#define GT_SMEM (GB_BYTES + 4 * GA_BYTES)
#define HG_SMEM (B_BYTES + 2 * HA_BYTES)
#define GRIDX 18                      // 18*8 = 144 CTAs <= 148 SMs: single wave
#define GTILES ((NSUB + 63) / 64)
#define HTILES ((NSUB + 127) / 128)

// ---------------- scratch ---------------------------------------------------
__device__ __align__(16) __half g_Yh[(long)TT * NSUB * HD];
__device__ __align__(16) __half g_Eh[(long)TT * NSUB * HD];
__device__ __align__(16) __half g_Wt[24 * 256 * LDB];
__device__ __align__(16) __half g_items[(long)ITEM_NUM * 256];
__device__ __align__(16) __half g_dys[(long)ITEM_DY_NUM * 256];
__device__ __align__(16) __half g_Xs[(long)TT * NSUB * 256];

__device__ int   g_cnt[TT * NSUB];
__device__ int   g_ptrA[TT * (NSUB + 1)];
__device__ int   g_posA[TT * NSUB];
__device__ int   g_ci[TT * NNZG];
__device__ float g_cvv[TT * NNZG];

__device__ int   e_cnt[TT * MSUB];
__device__ int   e_ptrA[TT * (MSUB + 1)];
__device__ int   e_posA[TT * MSUB];
__device__ int   e_ci[TT * NNZE];
__device__ float e_cvv[TT * NNZE];

// ---------------- helpers ---------------------------------------------------
__device__ __forceinline__ uint32_t smem_u32(const void* p) {
    uint32_t a;
    asm("{ .reg .u64 t; cvta.to.shared.u64 t, %1; cvt.u32.u64 %0, t; }" : "=r"(a) : "l"(p));
    return a;
}
__device__ __forceinline__ void ldsm4(uint32_t* r, uint32_t addr) {
    asm volatile("ldmatrix.sync.aligned.m8n8.x4.shared.b16 {%0,%1,%2,%3}, [%4];"
                 : "=r"(r[0]), "=r"(r[1]), "=r"(r[2]), "=r"(r[3]) : "r"(addr));
}
__device__ __forceinline__ void ldsm4t(uint32_t* r, uint32_t addr) {
    asm volatile("ldmatrix.sync.aligned.m8n8.x4.trans.shared.b16 {%0,%1,%2,%3}, [%4];"
                 : "=r"(r[0]), "=r"(r[1]), "=r"(r[2]), "=r"(r[3]) : "r"(addr));
}
__device__ __forceinline__ void mma16816(float* c, const uint32_t* a, const uint32_t* b) {
    asm volatile("mma.sync.aligned.m16n8k16.row.col.f32.f16.f16.f32 "
                 "{%0,%1,%2,%3}, {%4,%5,%6,%7}, {%8,%9}, {%0,%1,%2,%3};"
                 : "+f"(c[0]), "+f"(c[1]), "+f"(c[2]), "+f"(c[3])
                 : "r"(a[0]), "r"(a[1]), "r"(a[2]), "r"(a[3]), "r"(b[0]), "r"(b[1]));
}
__device__ __forceinline__ void split4h(float4 v, uint2& hi, uint2& lo) {
    __half h[4], l[4];
    float x[4] = {v.x, v.y, v.z, v.w};
#pragma unroll
    for (int j = 0; j < 4; j++) {
        h[j] = __float2half(x[j]);
        l[j] = __float2half(x[j] - __half2float(h[j]));
    }
    hi = *(uint2*)h; lo = *(uint2*)l;
}
#define CP16(dst, src) asm volatile("cp.async.cg.shared.global [%0], [%1], 16;" :: "r"(dst), "l"(src))
#define CP_COMMIT()    asm volatile("cp.async.commit_group;" ::: "memory")
#define CP_WAIT1()     asm volatile("cp.async.wait_group 1;" ::: "memory")

// ---------------- CSR build --------------------------------------------------
__global__ void zero_cnt_kernel() {
    int i = blockIdx.x * blockDim.x + threadIdx.x;
    if (i < TT * NSUB) g_cnt[i] = 0;
    if (i < TT * MSUB) e_cnt[i] = 0;
}

__global__ void hist_kernel(const int* __restrict__ rows, int* __restrict__ cnt,
                            int nnz, int nrows) {
    int i = blockIdx.x * blockDim.x + threadIdx.x;
    if (i >= TT * nnz) return;
    int t = i / nnz;
    atomicAdd(&cnt[t * nrows + rows[i]], 1);
}

__global__ __launch_bounds__(1024) void scan2_kernel() {
    int b = blockIdx.x;
    const int* cnt; int* ptr; int* pos; int n;
    if (b < TT) { cnt = g_cnt + b * NSUB; ptr = g_ptrA + b * (NSUB + 1); pos = g_posA + b * NSUB; n = NSUB; }
    else { int t = b - TT; cnt = e_cnt + t * MSUB; ptr = e_ptrA + t * (MSUB + 1); pos = e_posA + t * MSUB; n = MSUB; }
    __shared__ int wsum[32];
    __shared__ int s_carry;
    int tid = threadIdx.x, lane = tid & 31, wp = tid >> 5;
    if (tid == 0) s_carry = 0;
    __syncthreads();
    for (int base = 0; base < n; base += 8192) {
        int i0 = base + tid * 8;
        int v[8]; int sum = 0;
#pragma unroll
        for (int j = 0; j < 8; j++) { v[j] = (i0 + j < n) ? cnt[i0 + j] : 0; sum += v[j]; }
        int s = sum;
#pragma unroll
        for (int o = 1; o < 32; o <<= 1) { int u = __shfl_up_sync(0xffffffffu, s, o); if (lane >= o) s += u; }
        if (lane == 31) wsum[wp] = s;
        __syncthreads();
        if (wp == 0) {
            int t2 = wsum[lane];
            int ss = t2;
#pragma unroll
            for (int o = 1; o < 32; o <<= 1) { int u = __shfl_up_sync(0xffffffffu, ss, o); if (lane >= o) ss += u; }
            wsum[lane] = ss - t2;
        }
        __syncthreads();
        int run = s_carry + wsum[wp] + s - sum;
#pragma unroll
        for (int j = 0; j < 8; j++) {
            if (i0 + j < n) { ptr[i0 + j] = run; pos[i0 + j] = run; }
            run += v[j];
        }
        __syncthreads();
        if (tid == 1023) s_carry = run;
        __syncthreads();
    }
    if (tid == 0) ptr[n] = s_carry;
}

__global__ void scatter_kernel(const int* __restrict__ rows, const int* __restrict__ cols,
                               const float* __restrict__ vals, int* __restrict__ pos,
                               int* __restrict__ ci, float* __restrict__ cv,
                               int nnz, int nrows) {
    int i = blockIdx.x * blockDim.x + threadIdx.x;
    if (i >= TT * nnz) return;
    int t = i / nnz;
    int r = rows[i];
    int p = atomicAdd(&pos[t * nrows + r], 1);
    ci[(long)t * nnz + p] = cols[i];
    cv[(long)t * nnz + p] = vals[i];
}

// ---------------- SpMM: fp16 row gather -------------------------------------
__global__ void spmm_h(const int* __restrict__ ptr, const int* __restrict__ ci,
                       const float* __restrict__ cv,
                       const __half* __restrict__ xh, long xts,
                       float* __restrict__ yb, long yts,
                       __half* __restrict__ ys_split, __half* __restrict__ ys_hi,
                       const float* __restrict__ bias, int bstride,
                       int rows_per_t, int nnz, int do_relu) {
    int w = (blockIdx.x * blockDim.x + threadIdx.x) >> 5;
    int lane = threadIdx.x & 31;
    if (w >= TT * rows_per_t) return;
    int t = w / rows_per_t;
    int r = w - t * rows_per_t;
    const int* pp = ptr + t * (rows_per_t + 1);
    int jb = pp[r], je = pp[r + 1];
    const uint2* x2 = (const uint2*)(xh + (long)t * xts);
    const int*   cit = ci + (long)t * nnz;
    const float* cvt = cv + (long)t * nnz;
    float4 acc = make_float4(0.f, 0.f, 0.f, 0.f);
    float vsum = 0.f;
    int j = jb;
    for (; j + 4 <= je; j += 4) {
        int c0 = __ldg(cit + j),     c1 = __ldg(cit + j + 1);
        int c2 = __ldg(cit + j + 2), c3 = __ldg(cit + j + 3);
        float v0 = __ldg(cvt + j),     v1 = __ldg(cvt + j + 1);
        float v2 = __ldg(cvt + j + 2), v3 = __ldg(cvt + j + 3);
        uint2 u0 = x2[(long)c0 * 32 + lane];
        uint2 u1 = x2[(long)c1 * 32 + lane];
        uint2 u2 = x2[(long)c2 * 32 + lane];
        uint2 u3 = x2[(long)c3 * 32 + lane];
        vsum += v0 + v1 + v2 + v3;
        float2 a0 = __half22float2(*(__half2*)&u0.x), b0 = __half22float2(*(__half2*)&u0.y);
        float2 a1 = __half22float2(*(__half2*)&u1.x), b1 = __half22float2(*(__half2*)&u1.y);
        float2 a2 = __half22float2(*(__half2*)&u2.x), b2 = __half22float2(*(__half2*)&u2.y);
        float2 a3 = __half22float2(*(__half2*)&u3.x), b3 = __half22float2(*(__half2*)&u3.y);
        acc.x += v0 * a0.x + v1 * a1.x + v2 * a2.x + v3 * a3.x;
        acc.y += v0 * a0.y + v1 * a1.y + v2 * a2.y + v3 * a3.y;
        acc.z += v0 * b0.x + v1 * b1.x + v2 * b2.x + v3 * b3.x;
        acc.w += v0 * b0.y + v1 * b1.y + v2 * b2.y + v3 * b3.y;
    }
    for (; j < je; j++) {
        int   c0 = __ldg(cit + j);
        float v0 = __ldg(cvt + j);
        uint2 u0 = x2[(long)c0 * 32 + lane];
        float2 a0 = __half22float2(*(__half2*)&u0.x), b0 = __half22float2(*(__half2*)&u0.y);
        vsum += v0;
        acc.x += v0 * a0.x; acc.y += v0 * a0.y;
        acc.z += v0 * b0.x; acc.w += v0 * b0.y;
    }
    if (bias) {
        float4 bv = ((const float4*)(bias + (long)t * bstride))[lane];
        acc.x += vsum * bv.x; acc.y += vsum * bv.y; acc.z += vsum * bv.z; acc.w += vsum * bv.w;
    }
    if (do_relu) {
        acc.x = fmaxf(acc.x, 0.f); acc.y = fmaxf(acc.y, 0.f);
        acc.z = fmaxf(acc.z, 0.f); acc.w = fmaxf(acc.w, 0.f);
    }
    if (ys_split) {
        uint2 hi, lo; split4h(acc, hi, lo);
        __half* yr = ys_split + ((long)t * rows_per_t + r) * 256;
        *(uint2*)(yr + lane * 4) = hi;
        *(uint2*)(yr + 128 + lane * 4) = lo;
    }
    if (ys_hi) {
        uint2 hp;
        *(__half2*)&hp.x = __floats2half2_rn(acc.x, acc.y);
        *(__half2*)&hp.y = __floats2half2_rn(acc.z, acc.w);
        ((uint2*)(ys_hi + ((long)t * rows_per_t + r) * HD))[lane] = hp;
    }
    if (yb)
        ((float4*)(yb + (long)t * yts))[r * 32 + lane] = acc;
}

// ---------------- prep_w ----------------------------------------------------
__global__ __launch_bounds__(256) void prep_w(const float* __restrict__ Wg,
                                              const float* __restrict__ Wh) {
    int b = blockIdx.x, t = b / 3, s = b % 3;
    int tid = threadIdx.x;
    const float* W = (s == 0) ? Wg + (long)t * 16384 : Wh + ((long)t * 2 + (s - 1)) * 16384;
    __half* dst = g_Wt + (long)b * 256 * LDB;
    const float4* w4 = (const float4*)W;
    for (int i = tid; i < 4096; i += 256) {
        int k = i >> 5, c4 = (i & 31) * 4;
        uint2 hi, lo; split4h(w4[i], hi, lo);
        *(uint2*)(dst + k * LDB + c4) = hi;
        *(uint2*)(dst + (k + 128) * LDB + c4) = lo;
    }
}

// ---------------- prep_tables -----------------------------------------------
__global__ __launch_bounds__(256) void prep_tables(const float* __restrict__ ib,
                                                   const float* __restrict__ dt) {
    long i = (long)blockIdx.x * blockDim.x + threadIdx.x;
    const long NI = (long)ITEM_NUM * 32;
    const long ND = (long)ITEM_DY_NUM * 32;
    if (i < NI) {
        long row = i >> 5; int c4 = (int)(i & 31) * 4;
        uint2 hi, lo; split4h(((const float4*)ib)[i], hi, lo);
        *(uint2*)(g_items + row * 256 + c4) = hi;
        *(uint2*)(g_items + row * 256 + 128 + c4) = lo;
    } else if (i < NI + ND) {
        long j = i - NI;
        long row = j >> 5; int c4 = (int)(j & 31) * 4;
        uint2 hi, lo; split4h(((const float4*)dt)[j], hi, lo);
        *(uint2*)(g_dys + row * 256 + c4) = hi;
        *(uint2*)(g_dys + row * 256 + 128 + c4) = lo;
    }
}

// ---------------- gate: 1-term hi*hi logits, M=64 ---------------------------
__global__ __launch_bounds__(512, 1) void gate_mm(
    const float* __restrict__ bg,
    const int* __restrict__ rev_i, const int* __restrict__ rev_lat) {
    extern __shared__ char sm[];
    uint32_t smbU = smem_u32(sm);
    int t = blockIdx.y;
    int tid = threadIdx.x, lane = tid & 31, wid = tid >> 5;
    int wm = wid & 1, wn = wid >> 1;

    {
        const char* bsrc = (const char*)(g_Wt + (long)(t * 3) * 256 * LDB);
        for (int q = tid; q < GB_BYTES / 16; q += 512)
            CP16(smbU + q * 16, bsrc + q * 16);
    }
    auto fillA = [&](int p, int tile) {
        int rbase = tile * 64;
        uint32_t aBase = smbU + GB_BYTES + p * 2 * GA_BYTES;
        for (int i = tid; i < 4096; i += 512) {
            int r128 = i >> 5, ch = i & 31;
            int which = r128 >> 6, r = r128 & 63;
            int row = rbase + r; if (row >= NSUB) row = NSUB - 1;
            int gidx = which ? __ldg(rev_lat + t * NSUB + row) : __ldg(rev_i + t * NSUB + row);
            const char* src = (const char*)((which ? g_dys : g_items) + (long)gidx * 256) + ch * 16;
            CP16(aBase + which * GA_BYTES + r * 528 + ch * 16, src);
        }
    };

    int i0 = blockIdx.x;
    fillA(0, i0);
    CP_COMMIT();

    int buf = 0;
    for (int i = i0; i < GTILES; i += GRIDX) {
        int nxt = i + GRIDX;
        if (nxt < GTILES) fillA(buf ^ 1, nxt);
        CP_COMMIT();
        CP_WAIT1();
        __syncthreads();

        float acc0[2][2][4], acc1[2][2][4];
#pragma unroll
        for (int mi = 0; mi < 2; mi++)
#pragma unroll
            for (int nj = 0; nj < 2; nj++)
#pragma unroll
                for (int q = 0; q < 4; q++) { acc0[mi][nj][q] = 0.f; acc1[mi][nj][q] = 0.f; }

        uint32_t a0Base = smbU + GB_BYTES + buf * 2 * GA_BYTES;
        uint32_t a1Base = a0Base + GA_BYTES;
#pragma unroll
        for (int ks = 0; ks < 8; ks++) {
            int k = ks * 16;
            uint32_t a0h[2][4], a1h[2][4], bb[4];
#pragma unroll
            for (int mi = 0; mi < 2; mi++) {
                uint32_t off = ((wm * 32 + mi * 16 + (lane & 15)) * LDA + k + (lane >> 4) * 8) * 2;
                ldsm4(a0h[mi], a0Base + off);
                ldsm4(a1h[mi], a1Base + off);
            }
            ldsm4t(bb, smbU + ((k + (lane & 15)) * LDB + wn * 16 + (lane >> 4) * 8) * 2);
#pragma unroll
            for (int mi = 0; mi < 2; mi++)
#pragma unroll
                for (int nj = 0; nj < 2; nj++) {
                    mma16816(acc0[mi][nj], a0h[mi], &bb[nj * 2]);
                    mma16816(acc1[mi][nj], a1h[mi], &bb[nj * 2]);
                }
        }

        {
            const __half* A0h = (const __half*)(sm + GB_BYTES + buf * 2 * GA_BYTES);
            const __half* A1h = A0h + GA_BYTES / 2;
            int rbase = i * 64;
#pragma unroll
            for (int mi = 0; mi < 2; mi++)
#pragma unroll
                for (int nj = 0; nj < 2; nj++)
#pragma unroll
                    for (int h = 0; h < 2; h++) {
                        int r = wm * 32 + mi * 16 + (lane >> 2) + h * 8;
                        int grow = rbase + r;
                        if (grow >= NSUB) continue;
                        int col = wn * 16 + nj * 8 + (lane & 3) * 2;
                        float pa0 = acc0[mi][nj][h * 2], pa1 = acc0[mi][nj][h * 2 + 1];
                        float pb0 = acc1[mi][nj][h * 2], pb1 = acc1[mi][nj][h * 2 + 1];
                        __half2 h0 = *(const __half2*)(A0h + r * LDA + col);
                        __half2 l0 = *(const __half2*)(A0h + r * LDA + 128 + col);
                        __half2 h1 = *(const __half2*)(A1h + r * LDA + col);
                        __half2 l1 = *(const __half2*)(A1h + r * LDA + 128 + col);
                        float x00 = __half2float(h0.x) + __half2float(l0.x);
                        float x01 = __half2float(h0.y) + __half2float(l0.y);
                        float x10 = __half2float(h1.x) + __half2float(l1.x);
                        float x11 = __half2float(h1.y) + __half2float(l1.y);
                        float bv0 = __ldg(bg + t * HD + col), bv1 = __ldg(bg + t * HD + col + 1);
                        float s0a = __fdividef(1.f, 1.f + __expf(-(pa0 + bv0)));
                        float s0b = __fdividef(1.f, 1.f + __expf(-(pb0 + bv0)));
                        float s1a = __fdividef(1.f, 1.f + __expf(-(pa1 + bv1)));
                        float s1b = __fdividef(1.f, 1.f + __expf(-(pb1 + bv1)));
                        float ox = x00 * s0a + x10 * s0b;
                        float oy = x01 * s1a + x11 * s1b;
                        __half hx = __float2half(ox), hy = __float2half(oy);
                        __half lx = __float2half(ox - __half2float(hx));
                        __half ly = __float2half(oy - __half2float(hy));
                        __half* yr = g_Xs + ((long)t * NSUB + grow) * 256;
                        __half2 hp, lp;
                        hp.x = hx; hp.y = hy; lp.x = lx; lp.y = ly;
                        *(__half2*)(yr + col) = hp;
                        *(__half2*)(yr + 128 + col) = lp;
                    }
        }
        __syncthreads();
        buf ^= 1;
    }
}

// ---------------- hgnn: 3-term single-pass, fp16 output ---------------------
__global__ __launch_bounds__(512, 1) void hgnn_mm(int l) {
    extern __shared__ char sm[];
    uint32_t smbU = smem_u32(sm);
    int t = blockIdx.y;
    int tid = threadIdx.x, lane = tid & 31, wid = tid >> 5;
    int wm = wid & 3, wn = wid >> 2;

    {
        const char* bsrc = (const char*)(g_Wt + (long)(t * 3 + 1 + l) * 256 * LDB);
        for (int q = tid; q < B_BYTES / 16; q += 512)
            CP16(smbU + q * 16, bsrc + q * 16);
    }
    auto fillA = [&](int p, int tile) {
        int rbase = tile * 128;
        uint32_t aBase = smbU + B_BYTES + p * HA_BYTES;
        const __half* xs = g_Xs + (long)t * NSUB * 256;
        for (int i = tid; i < 4096; i += 512) {
            int r = i >> 5, ch = i & 31;
            int row = rbase + r; if (row >= NSUB) row = 0;
            CP16(aBase + r * 528 + ch * 16, (const char*)(xs + (long)row * 256) + ch * 16);
        }
    };

    int i0 = blockIdx.x;
    fillA(0, i0);
    CP_COMMIT();

    int buf = 0;
    for (int i = i0; i < HTILES; i += GRIDX) {
        int nxt = i + GRIDX;
        if (nxt < HTILES) fillA(buf ^ 1, nxt);
        CP_COMMIT();
        CP_WAIT1();
        __syncthreads();

        float acc[2][4][4];
#pragma unroll
        for (int mi = 0; mi < 2; mi++)
#pragma unroll
            for (int nj = 0; nj < 4; nj++)
#pragma unroll
                for (int q = 0; q < 4; q++) acc[mi][nj][q] = 0.f;

        uint32_t aBase = smbU + B_BYTES + buf * HA_BYTES;
#pragma unroll
        for (int ks = 0; ks < 8; ks++) {
            int k = ks * 16;
            uint32_t ah[2][4], al[2][4], bh[2][4], bl[2][4];
#pragma unroll
            for (int mi = 0; mi < 2; mi++) {
                uint32_t off = ((wm * 32 + mi * 16 + (lane & 15)) * LDA + k + (lane >> 4) * 8) * 2;
                ldsm4(ah[mi], aBase + off);
                ldsm4(al[mi], aBase + off + 256);
            }
#pragma unroll
            for (int p = 0; p < 2; p++) {
                uint32_t off = ((k + (lane & 15)) * LDB + wn * 32 + p * 16 + (lane >> 4) * 8) * 2;
                ldsm4t(bh[p], smbU + off);
                ldsm4t(bl[p], smbU + off + 128 * LDB * 2);
            }
#pragma unroll
            for (int mi = 0; mi < 2; mi++)
#pragma unroll
                for (int nj = 0; nj < 4; nj++) {
                    const uint32_t* bhf = &bh[nj >> 1][(nj & 1) * 2];
                    const uint32_t* blf = &bl[nj >> 1][(nj & 1) * 2];
                    mma16816(acc[mi][nj], ah[mi], bhf);
                    mma16816(acc[mi][nj], al[mi], bhf);
                    mma16816(acc[mi][nj], ah[mi], blf);
                }
        }

        __half* Yt = g_Yh + (long)t * NSUB * HD;
        int mbase = i * 128;
#pragma unroll
        for (int mi = 0; mi < 2; mi++) {
            int r0 = mbase + wm * 32 + mi * 16 + (lane >> 2);
#pragma unroll
            for (int nj = 0; nj < 4; nj++) {
                int col = wn * 32 + nj * 8 + (lane & 3) * 2;
                if (r0 < NSUB)
                    *(__half2*)(Yt + (long)r0 * HD + col) = __floats2half2_rn(acc[mi][nj][0], acc[mi][nj][1]);
                if (r0 + 8 < NSUB)
                    *(__half2*)(Yt + (long)(r0 + 8) * HD + col) = __floats2half2_rn(acc[mi][nj][2], acc[mi][nj][3]);
            }
        }
        __syncthreads();
        buf ^= 1;
    }
}

// ---------------- host ------------------------------------------------------
static void* sym_addr(const void* sym) { void* p = 0; cudaGetSymbolAddress(&p, sym); return p; }

extern "C" void kernel_launch(void* const* d_in, const int* in_sizes, int n_in,
                              void* d_out, int out_size) {
    const float* item_base = (const float*)d_in[0];
    const float* user_base = (const float*)d_in[1];
    const float* dy_tab    = (const float*)d_in[2];
    const float* Wg        = (const float*)d_in[3];
    const float* bg        = (const float*)d_in[4];
    const float* Wh        = (const float*)d_in[5];
    const float* bh        = (const float*)d_in[6];
    const float* gv        = (const float*)d_in[7];
    const float* ev        = (const float*)d_in[8];
    const int*   rev_i     = (const int*)d_in[9];
    const int*   rev_lat   = (const int*)d_in[10];
    const int*   grows     = (const int*)d_in[11];
    const int*   gcols     = (const int*)d_in[12];
    const int*   erows     = (const int*)d_in[13];
    const int*   ecols     = (const int*)d_in[14];
    float* out = (float*)d_out;

    static cudaStream_t s2 = 0;
    static cudaEvent_t evF = 0, evJ = 0;
    if (!s2) {
        cudaStreamCreateWithFlags(&s2, cudaStreamNonBlocking);
        cudaEventCreateWithFlags(&evF, cudaEventDisableTiming);
        cudaEventCreateWithFlags(&evJ, cudaEventDisableTiming);
        cudaFuncSetAttribute(hgnn_mm, cudaFuncAttributeMaxDynamicSharedMemorySize, HG_SMEM);
        cudaFuncSetAttribute(gate_mm, cudaFuncAttributeMaxDynamicSharedMemorySize, GT_SMEM);
    }

    int* d_gptr = (int*)sym_addr(g_ptrA);
    int* d_gpos = (int*)sym_addr(g_posA);
    int* d_gci  = (int*)sym_addr(g_ci);
    float* d_gcv = (float*)sym_addr(g_cvv);
    int* d_eptr = (int*)sym_addr(e_ptrA);
    int* d_epos = (int*)sym_addr(e_posA);
    int* d_eci  = (int*)sym_addr(e_ci);
    float* d_ecv = (float*)sym_addr(e_cvv);
    __half* d_Yh = (__half*)sym_addr(g_Yh);
    __half* d_Eh = (__half*)sym_addr(g_Eh);
    __half* d_Xs = (__half*)sym_addr(g_Xs);
    int* d_gcnt = (int*)sym_addr(g_cnt);
    int* d_ecnt = (int*)sym_addr(e_cnt);

    dim3 tgrid(GRIDX, TT);

    // fork: CSR build on s2 overlaps the dense prologue
    cudaEventRecord(evF, 0);
    cudaStreamWaitEvent(s2, evF, 0);

    // launch indices (memcpys count): gate_mm lands at 5 for ncu "-s 5 -c 1"
    cudaMemcpyAsync(out, user_base, (size_t)USER_NUM * HD * sizeof(float),
                    cudaMemcpyDeviceToDevice, 0);                                   // 0
    cudaMemcpyAsync(out + (size_t)(USER_NUM + TT * MSUB) * HD, item_base,
                    (size_t)ITEM_NUM * HD * sizeof(float), cudaMemcpyDeviceToDevice, 0); // 1
    prep_w<<<24, 256>>>(Wg, Wh);                                                    // 2
    prep_tables<<<((ITEM_NUM + ITEM_DY_NUM) * 32 + 255) / 256, 256>>>(item_base, dy_tab); // 3
    zero_cnt_kernel<<<(TT * NSUB + 255) / 256, 256, 0, s2>>>();                     // 4
    gate_mm<<<tgrid, 512, GT_SMEM>>>(bg, rev_i, rev_lat);                           // 5 <- profiled
    hist_kernel<<<(TT * NNZG + 255) / 256, 256, 0, s2>>>(grows, d_gcnt, NNZG, NSUB);
    hist_kernel<<<(TT * NNZE + 255) / 256, 256, 0, s2>>>(erows, d_ecnt, NNZE, MSUB);
    scan2_kernel<<<16, 1024, 0, s2>>>();
    scatter_kernel<<<(TT * NNZG + 255) / 256, 256, 0, s2>>>(grows, gcols, gv, d_gpos, d_gci, d_gcv, NNZG, NSUB);
    scatter_kernel<<<(TT * NNZE + 255) / 256, 256, 0, s2>>>(erows, ecols, ev, d_epos, d_eci, d_ecv, NNZE, MSUB);
    cudaEventRecord(evJ, s2);

    hgnn_mm<<<tgrid, 512, HG_SMEM>>>(0);

    // join: SpMM needs CSR
    cudaStreamWaitEvent(0, evJ, 0);

    float* out_item = out + (size_t)(USER_NUM + TT * MSUB + ITEM_NUM) * HD;
    float* out_user = out + (size_t)USER_NUM * HD;

    spmm_h<<<(TT * NSUB * 32) / 256, 256>>>(d_gptr, d_gci, d_gcv,
        d_Yh, (long)NSUB * HD, (float*)nullptr, 0, d_Xs, (__half*)nullptr,
        bh + 0 * HD, 2 * HD, NSUB, NNZG, 1);
    hgnn_mm<<<tgrid, 512, HG_SMEM>>>(1);
    spmm_h<<<(TT * NSUB * 32) / 256, 256>>>(d_gptr, d_gci, d_gcv,
        d_Yh, (long)NSUB * HD, out_item, (long)NSUB * HD, (__half*)nullptr, d_Eh,
        bh + 1 * HD, 2 * HD, NSUB, NNZG, 1);
    spmm_h<<<(TT * MSUB * 32) / 256, 256>>>(d_eptr, d_eci, d_ecv,
        d_Eh, (long)NSUB * HD, out_user, (long)MSUB * HD, (__half*)nullptr, (__half*)nullptr,
        (const float*)nullptr, 0, MSUB, NNZE, 0);
}

// round 15
// speedup vs baseline: 1.1400x; 1.1115x over previous
#include <cuda_runtime.h>
#include <cuda_fp16.h>
#include <cstdint>

#define TT 8
#define NSUB 20000
#define MSUB 5000
#define HD 128
#define NNZG 200000
#define NNZE 100000
#define ITEM_NUM 40000
#define USER_NUM 10000
#define ITEM_DY_NUM 60000

#define LDA2 136                      // A row stride (halves): 272B, conflict-free
#define LDB 136
#define B_BYTES (256 * LDB * 2)       // 69632 (hgnn B: hi+lo)
#define GB_BYTES (128 * LDB * 2)      // 34816 (gate B: hi only)
#define GA_BYTES (64 * LDA2 * 2)      // 17408
#define HA_BYTES (128 * LDA2 * 2)     // 34816
#define GT_SMEM (GB_BYTES + 4 * GA_BYTES)  // 104448
#define HG_SMEM (B_BYTES + 2 * HA_BYTES)   // 139264
#define GRIDX 18
#define GTILES ((NSUB + 63) / 64)
#define HTILES ((NSUB + 127) / 128)

// ---------------- scratch ---------------------------------------------------
__device__ __align__(16) __half g_Yh[(long)TT * NSUB * HD];
__device__ __align__(16) __half g_Eh[(long)TT * NSUB * HD];
__device__ __align__(16) __half g_Wt[24 * 256 * LDB];
__device__ __align__(16) __half g_items[(long)ITEM_NUM * HD];
__device__ __align__(16) __half g_dys[(long)ITEM_DY_NUM * HD];
__device__ __align__(16) __half g_Xs[(long)TT * NSUB * HD];

__device__ int   g_cnt[TT * NSUB];
__device__ int   g_ptrA[TT * (NSUB + 1)];
__device__ int   g_posA[TT * NSUB];
__device__ int   g_ci[TT * NNZG];
__device__ float g_cvv[TT * NNZG];

__device__ int   e_cnt[TT * MSUB];
__device__ int   e_ptrA[TT * (MSUB + 1)];
__device__ int   e_posA[TT * MSUB];
__device__ int   e_ci[TT * NNZE];
__device__ float e_cvv[TT * NNZE];

// ---------------- helpers ---------------------------------------------------
__device__ __forceinline__ uint32_t smem_u32(const void* p) {
    uint32_t a;
    asm("{ .reg .u64 t; cvta.to.shared.u64 t, %1; cvt.u32.u64 %0, t; }" : "=r"(a) : "l"(p));
    return a;
}
__device__ __forceinline__ void ldsm4(uint32_t* r, uint32_t addr) {
    asm volatile("ldmatrix.sync.aligned.m8n8.x4.shared.b16 {%0,%1,%2,%3}, [%4];"
                 : "=r"(r[0]), "=r"(r[1]), "=r"(r[2]), "=r"(r[3]) : "r"(addr));
}
__device__ __forceinline__ void ldsm4t(uint32_t* r, uint32_t addr) {
    asm volatile("ldmatrix.sync.aligned.m8n8.x4.trans.shared.b16 {%0,%1,%2,%3}, [%4];"
                 : "=r"(r[0]), "=r"(r[1]), "=r"(r[2]), "=r"(r[3]) : "r"(addr));
}
__device__ __forceinline__ void mma16816(float* c, const uint32_t* a, const uint32_t* b) {
    asm volatile("mma.sync.aligned.m16n8k16.row.col.f32.f16.f16.f32 "
                 "{%0,%1,%2,%3}, {%4,%5,%6,%7}, {%8,%9}, {%0,%1,%2,%3};"
                 : "+f"(c[0]), "+f"(c[1]), "+f"(c[2]), "+f"(c[3])
                 : "r"(a[0]), "r"(a[1]), "r"(a[2]), "r"(a[3]), "r"(b[0]), "r"(b[1]));
}
__device__ __forceinline__ void split4h(float4 v, uint2& hi, uint2& lo) {
    __half h[4], l[4];
    float x[4] = {v.x, v.y, v.z, v.w};
#pragma unroll
    for (int j = 0; j < 4; j++) {
        h[j] = __float2half(x[j]);
        l[j] = __float2half(x[j] - __half2float(h[j]));
    }
    hi = *(uint2*)h; lo = *(uint2*)l;
}
#define CP16(dst, src) asm volatile("cp.async.cg.shared.global [%0], [%1], 16;" :: "r"(dst), "l"(src))
#define CP_COMMIT()    asm volatile("cp.async.commit_group;" ::: "memory")
#define CP_WAIT1()     asm volatile("cp.async.wait_group 1;" ::: "memory")

// ---------------- CSR build --------------------------------------------------
__global__ void zero_cnt_kernel() {
    int i = blockIdx.x * blockDim.x + threadIdx.x;
    if (i < TT * NSUB) g_cnt[i] = 0;
    if (i < TT * MSUB) e_cnt[i] = 0;
}

__global__ void hist_kernel(const int* __restrict__ rows, int* __restrict__ cnt,
                            int nnz, int nrows) {
    int i = blockIdx.x * blockDim.x + threadIdx.x;
    if (i >= TT * nnz) return;
    int t = i / nnz;
    atomicAdd(&cnt[t * nrows + rows[i]], 1);
}

__global__ __launch_bounds__(1024) void scan2_kernel() {
    int b = blockIdx.x;
    const int* cnt; int* ptr; int* pos; int n;
    if (b < TT) { cnt = g_cnt + b * NSUB; ptr = g_ptrA + b * (NSUB + 1); pos = g_posA + b * NSUB; n = NSUB; }
    else { int t = b - TT; cnt = e_cnt + t * MSUB; ptr = e_ptrA + t * (MSUB + 1); pos = e_posA + t * MSUB; n = MSUB; }
    __shared__ int wsum[32];
    __shared__ int s_carry;
    int tid = threadIdx.x, lane = tid & 31, wp = tid >> 5;
    if (tid == 0) s_carry = 0;
    __syncthreads();
    for (int base = 0; base < n; base += 8192) {
        int i0 = base + tid * 8;
        int v[8]; int sum = 0;
#pragma unroll
        for (int j = 0; j < 8; j++) { v[j] = (i0 + j < n) ? cnt[i0 + j] : 0; sum += v[j]; }
        int s = sum;
#pragma unroll
        for (int o = 1; o < 32; o <<= 1) { int u = __shfl_up_sync(0xffffffffu, s, o); if (lane >= o) s += u; }
        if (lane == 31) wsum[wp] = s;
        __syncthreads();
        if (wp == 0) {
            int t2 = wsum[lane];
            int ss = t2;
#pragma unroll
            for (int o = 1; o < 32; o <<= 1) { int u = __shfl_up_sync(0xffffffffu, ss, o); if (lane >= o) ss += u; }
            wsum[lane] = ss - t2;
        }
        __syncthreads();
        int run = s_carry + wsum[wp] + s - sum;
#pragma unroll
        for (int j = 0; j < 8; j++) {
            if (i0 + j < n) { ptr[i0 + j] = run; pos[i0 + j] = run; }
            run += v[j];
        }
        __syncthreads();
        if (tid == 1023) s_carry = run;
        __syncthreads();
    }
    if (tid == 0) ptr[n] = s_carry;
}

__global__ void scatter_kernel(const int* __restrict__ rows, const int* __restrict__ cols,
                               const float* __restrict__ vals, int* __restrict__ pos,
                               int* __restrict__ ci, float* __restrict__ cv,
                               int nnz, int nrows) {
    int i = blockIdx.x * blockDim.x + threadIdx.x;
    if (i >= TT * nnz) return;
    int t = i / nnz;
    int r = rows[i];
    int p = atomicAdd(&pos[t * nrows + r], 1);
    ci[(long)t * nnz + p] = cols[i];
    cv[(long)t * nnz + p] = vals[i];
}

// ---------------- SpMM: fp16 row gather, fp16/fp32 outputs ------------------
__global__ void spmm_h(const int* __restrict__ ptr, const int* __restrict__ ci,
                       const float* __restrict__ cv,
                       const __half* __restrict__ xh, long xts,
                       float* __restrict__ yb, long yts,
                       __half* __restrict__ ys_hi,
                       const float* __restrict__ bias, int bstride,
                       int rows_per_t, int nnz, int do_relu) {
    int w = (blockIdx.x * blockDim.x + threadIdx.x) >> 5;
    int lane = threadIdx.x & 31;
    if (w >= TT * rows_per_t) return;
    int t = w / rows_per_t;
    int r = w - t * rows_per_t;
    const int* pp = ptr + t * (rows_per_t + 1);
    int jb = pp[r], je = pp[r + 1];
    const uint2* x2 = (const uint2*)(xh + (long)t * xts);
    const int*   cit = ci + (long)t * nnz;
    const float* cvt = cv + (long)t * nnz;
    float4 acc = make_float4(0.f, 0.f, 0.f, 0.f);
    float vsum = 0.f;
    int j = jb;
    for (; j + 4 <= je; j += 4) {
        int c0 = __ldg(cit + j),     c1 = __ldg(cit + j + 1);
        int c2 = __ldg(cit + j + 2), c3 = __ldg(cit + j + 3);
        float v0 = __ldg(cvt + j),     v1 = __ldg(cvt + j + 1);
        float v2 = __ldg(cvt + j + 2), v3 = __ldg(cvt + j + 3);
        uint2 u0 = x2[(long)c0 * 32 + lane];
        uint2 u1 = x2[(long)c1 * 32 + lane];
        uint2 u2 = x2[(long)c2 * 32 + lane];
        uint2 u3 = x2[(long)c3 * 32 + lane];
        vsum += v0 + v1 + v2 + v3;
        float2 a0 = __half22float2(*(__half2*)&u0.x), b0 = __half22float2(*(__half2*)&u0.y);
        float2 a1 = __half22float2(*(__half2*)&u1.x), b1 = __half22float2(*(__half2*)&u1.y);
        float2 a2 = __half22float2(*(__half2*)&u2.x), b2 = __half22float2(*(__half2*)&u2.y);
        float2 a3 = __half22float2(*(__half2*)&u3.x), b3 = __half22float2(*(__half2*)&u3.y);
        acc.x += v0 * a0.x + v1 * a1.x + v2 * a2.x + v3 * a3.x;
        acc.y += v0 * a0.y + v1 * a1.y + v2 * a2.y + v3 * a3.y;
        acc.z += v0 * b0.x + v1 * b1.x + v2 * b2.x + v3 * b3.x;
        acc.w += v0 * b0.y + v1 * b1.y + v2 * b2.y + v3 * b3.y;
    }
    for (; j < je; j++) {
        int   c0 = __ldg(cit + j);
        float v0 = __ldg(cvt + j);
        uint2 u0 = x2[(long)c0 * 32 + lane];
        float2 a0 = __half22float2(*(__half2*)&u0.x), b0 = __half22float2(*(__half2*)&u0.y);
        vsum += v0;
        acc.x += v0 * a0.x; acc.y += v0 * a0.y;
        acc.z += v0 * b0.x; acc.w += v0 * b0.y;
    }
    if (bias) {
        float4 bv = ((const float4*)(bias + (long)t * bstride))[lane];
        acc.x += vsum * bv.x; acc.y += vsum * bv.y; acc.z += vsum * bv.z; acc.w += vsum * bv.w;
    }
    if (do_relu) {
        acc.x = fmaxf(acc.x, 0.f); acc.y = fmaxf(acc.y, 0.f);
        acc.z = fmaxf(acc.z, 0.f); acc.w = fmaxf(acc.w, 0.f);
    }
    if (ys_hi) {
        uint2 hp;
        *(__half2*)&hp.x = __floats2half2_rn(acc.x, acc.y);
        *(__half2*)&hp.y = __floats2half2_rn(acc.z, acc.w);
        ((uint2*)(ys_hi + ((long)t * rows_per_t + r) * HD))[lane] = hp;
    }
    if (yb)
        ((float4*)(yb + (long)t * yts))[r * 32 + lane] = acc;
}

// ---------------- prep_w (weights: split hi/lo) -----------------------------
__global__ __launch_bounds__(256) void prep_w(const float* __restrict__ Wg,
                                              const float* __restrict__ Wh) {
    int b = blockIdx.x, t = b / 3, s = b % 3;
    int tid = threadIdx.x;
    const float* W = (s == 0) ? Wg + (long)t * 16384 : Wh + ((long)t * 2 + (s - 1)) * 16384;
    __half* dst = g_Wt + (long)b * 256 * LDB;
    const float4* w4 = (const float4*)W;
    for (int i = tid; i < 4096; i += 256) {
        int k = i >> 5, c4 = (i & 31) * 4;
        uint2 hi, lo; split4h(w4[i], hi, lo);
        *(uint2*)(dst + k * LDB + c4) = hi;
        *(uint2*)(dst + (k + 128) * LDB + c4) = lo;
    }
}

// ---------------- prep_tables: fp32 -> fp16 hi only -------------------------
__global__ __launch_bounds__(256) void prep_tables(const float* __restrict__ ib,
                                                   const float* __restrict__ dt) {
    long i = (long)blockIdx.x * blockDim.x + threadIdx.x;
    const long NI = (long)ITEM_NUM * 32;
    const long ND = (long)ITEM_DY_NUM * 32;
    if (i < NI) {
        float4 v = ((const float4*)ib)[i];
        uint2 hp;
        *(__half2*)&hp.x = __floats2half2_rn(v.x, v.y);
        *(__half2*)&hp.y = __floats2half2_rn(v.z, v.w);
        ((uint2*)g_items)[i] = hp;
    } else if (i < NI + ND) {
        long j = i - NI;
        float4 v = ((const float4*)dt)[j];
        uint2 hp;
        *(__half2*)&hp.x = __floats2half2_rn(v.x, v.y);
        *(__half2*)&hp.y = __floats2half2_rn(v.z, v.w);
        ((uint2*)g_dys)[j] = hp;
    }
}

// ---------------- gate: fp16 tiles, 1-term logits, M=64 ---------------------
__global__ __launch_bounds__(512, 1) void gate_mm(
    const float* __restrict__ bg,
    const int* __restrict__ rev_i, const int* __restrict__ rev_lat) {
    extern __shared__ char sm[];
    uint32_t smbU = smem_u32(sm);
    int t = blockIdx.y;
    int tid = threadIdx.x, lane = tid & 31, wid = tid >> 5;
    int wm = wid & 1, wn = wid >> 1;   // 2 x 8 warps (M=64, N=128)

    {
        const char* bsrc = (const char*)(g_Wt + (long)(t * 3) * 256 * LDB);
        for (int q = tid; q < GB_BYTES / 16; q += 512)
            CP16(smbU + q * 16, bsrc + q * 16);
    }
    // A tiles hi-only: 64 rows x 128 halves (16 chunks of 16B), stride 272B
    auto fillA = [&](int p, int tile) {
        int rbase = tile * 64;
        uint32_t aBase = smbU + GB_BYTES + p * 2 * GA_BYTES;
        for (int i = tid; i < 2048; i += 512) {
            int which = i >> 10;
            int r = (i & 1023) >> 4, ch = i & 15;
            int row = rbase + r; if (row >= NSUB) row = NSUB - 1;
            int gidx = which ? __ldg(rev_lat + t * NSUB + row) : __ldg(rev_i + t * NSUB + row);
            const char* src = (const char*)((which ? g_dys : g_items) + (long)gidx * HD) + ch * 16;
            CP16(aBase + which * GA_BYTES + r * (LDA2 * 2) + ch * 16, src);
        }
    };

    int i0 = blockIdx.x;
    fillA(0, i0);
    CP_COMMIT();

    int buf = 0;
    for (int i = i0; i < GTILES; i += GRIDX) {
        int nxt = i + GRIDX;
        if (nxt < GTILES) fillA(buf ^ 1, nxt);
        CP_COMMIT();
        CP_WAIT1();
        __syncthreads();

        float acc0[2][2][4], acc1[2][2][4];
#pragma unroll
        for (int mi = 0; mi < 2; mi++)
#pragma unroll
            for (int nj = 0; nj < 2; nj++)
#pragma unroll
                for (int q = 0; q < 4; q++) { acc0[mi][nj][q] = 0.f; acc1[mi][nj][q] = 0.f; }

        uint32_t a0Base = smbU + GB_BYTES + buf * 2 * GA_BYTES;
        uint32_t a1Base = a0Base + GA_BYTES;
#pragma unroll
        for (int ks = 0; ks < 8; ks++) {
            int k = ks * 16;
            uint32_t a0h[2][4], a1h[2][4], bb[4];
#pragma unroll
            for (int mi = 0; mi < 2; mi++) {
                uint32_t off = ((wm * 32 + mi * 16 + (lane & 15)) * LDA2 + k + (lane >> 4) * 8) * 2;
                ldsm4(a0h[mi], a0Base + off);
                ldsm4(a1h[mi], a1Base + off);
            }
            ldsm4t(bb, smbU + ((k + (lane & 15)) * LDB + wn * 16 + (lane >> 4) * 8) * 2);
#pragma unroll
            for (int mi = 0; mi < 2; mi++)
#pragma unroll
                for (int nj = 0; nj < 2; nj++) {
                    mma16816(acc0[mi][nj], a0h[mi], &bb[nj * 2]);
                    mma16816(acc1[mi][nj], a1h[mi], &bb[nj * 2]);
                }
        }

        {   // epilogue: x from fp16 smem, sigmoid mix, fp16 store
            const __half* A0h = (const __half*)(sm + GB_BYTES + buf * 2 * GA_BYTES);
            const __half* A1h = A0h + GA_BYTES / 2;
            int rbase = i * 64;
#pragma unroll
            for (int mi = 0; mi < 2; mi++)
#pragma unroll
                for (int nj = 0; nj < 2; nj++)
#pragma unroll
                    for (int h = 0; h < 2; h++) {
                        int r = wm * 32 + mi * 16 + (lane >> 2) + h * 8;
                        int grow = rbase + r;
                        if (grow >= NSUB) continue;
                        int col = wn * 16 + nj * 8 + (lane & 3) * 2;
                        float pa0 = acc0[mi][nj][h * 2], pa1 = acc0[mi][nj][h * 2 + 1];
                        float pb0 = acc1[mi][nj][h * 2], pb1 = acc1[mi][nj][h * 2 + 1];
                        float2 x0 = __half22float2(*(const __half2*)(A0h + r * LDA2 + col));
                        float2 x1 = __half22float2(*(const __half2*)(A1h + r * LDA2 + col));
                        float bv0 = __ldg(bg + t * HD + col), bv1 = __ldg(bg + t * HD + col + 1);
                        float s0a = __fdividef(1.f, 1.f + __expf(-(pa0 + bv0)));
                        float s0b = __fdividef(1.f, 1.f + __expf(-(pb0 + bv0)));
                        float s1a = __fdividef(1.f, 1.f + __expf(-(pa1 + bv1)));
                        float s1b = __fdividef(1.f, 1.f + __expf(-(pb1 + bv1)));
                        float ox = x0.x * s0a + x1.x * s0b;
                        float oy = x0.y * s1a + x1.y * s1b;
                        __half* yr = g_Xs + ((long)t * NSUB + grow) * HD;
                        *(__half2*)(yr + col) = __floats2half2_rn(ox, oy);
                    }
        }
        __syncthreads();
        buf ^= 1;
    }
}

// ---------------- hgnn: 2-term (a*wh + a*wl), fp16 A, M=128 -----------------
__global__ __launch_bounds__(512, 1) void hgnn_mm(int l) {
    extern __shared__ char sm[];
    uint32_t smbU = smem_u32(sm);
    int t = blockIdx.y;
    int tid = threadIdx.x, lane = tid & 31, wid = tid >> 5;
    int wm = wid & 3, wn = wid >> 2;   // 4 x 4 grid (128 x 128)

    {
        const char* bsrc = (const char*)(g_Wt + (long)(t * 3 + 1 + l) * 256 * LDB);
        for (int q = tid; q < B_BYTES / 16; q += 512)
            CP16(smbU + q * 16, bsrc + q * 16);
    }
    auto fillA = [&](int p, int tile) {
        int rbase = tile * 128;
        uint32_t aBase = smbU + B_BYTES + p * HA_BYTES;
        const __half* xs = g_Xs + (long)t * NSUB * HD;
        for (int i = tid; i < 2048; i += 512) {
            int r = i >> 4, ch = i & 15;
            int row = rbase + r; if (row >= NSUB) row = 0;
            CP16(aBase + r * (LDA2 * 2) + ch * 16, (const char*)(xs + (long)row * HD) + ch * 16);
        }
    };

    int i0 = blockIdx.x;
    fillA(0, i0);
    CP_COMMIT();

    int buf = 0;
    for (int i = i0; i < HTILES; i += GRIDX) {
        int nxt = i + GRIDX;
        if (nxt < HTILES) fillA(buf ^ 1, nxt);
        CP_COMMIT();
        CP_WAIT1();
        __syncthreads();

        float acc[2][4][4];
#pragma unroll
        for (int mi = 0; mi < 2; mi++)
#pragma unroll
            for (int nj = 0; nj < 4; nj++)
#pragma unroll
                for (int q = 0; q < 4; q++) acc[mi][nj][q] = 0.f;

        uint32_t aBase = smbU + B_BYTES + buf * HA_BYTES;
#pragma unroll
        for (int ks = 0; ks < 8; ks++) {
            int k = ks * 16;
            uint32_t ah[2][4], bh[2][4], bl[2][4];
#pragma unroll
            for (int mi = 0; mi < 2; mi++)
                ldsm4(ah[mi], aBase + ((wm * 32 + mi * 16 + (lane & 15)) * LDA2 + k + (lane >> 4) * 8) * 2);
#pragma unroll
            for (int p = 0; p < 2; p++) {
                uint32_t off = ((k + (lane & 15)) * LDB + wn * 32 + p * 16 + (lane >> 4) * 8) * 2;
                ldsm4t(bh[p], smbU + off);
                ldsm4t(bl[p], smbU + off + 128 * LDB * 2);
            }
#pragma unroll
            for (int mi = 0; mi < 2; mi++)
#pragma unroll
                for (int nj = 0; nj < 4; nj++) {
                    mma16816(acc[mi][nj], ah[mi], &bh[nj >> 1][(nj & 1) * 2]);
                    mma16816(acc[mi][nj], ah[mi], &bl[nj >> 1][(nj & 1) * 2]);
                }
        }

        __half* Yt = g_Yh + (long)t * NSUB * HD;
        int mbase = i * 128;
#pragma unroll
        for (int mi = 0; mi < 2; mi++) {
            int r0 = mbase + wm * 32 + mi * 16 + (lane >> 2);
#pragma unroll
            for (int nj = 0; nj < 4; nj++) {
                int col = wn * 32 + nj * 8 + (lane & 3) * 2;
                if (r0 < NSUB)
                    *(__half2*)(Yt + (long)r0 * HD + col) = __floats2half2_rn(acc[mi][nj][0], acc[mi][nj][1]);
                if (r0 + 8 < NSUB)
                    *(__half2*)(Yt + (long)(r0 + 8) * HD + col) = __floats2half2_rn(acc[mi][nj][2], acc[mi][nj][3]);
            }
        }
        __syncthreads();
        buf ^= 1;
    }
}

// ---------------- host ------------------------------------------------------
static void* sym_addr(const void* sym) { void* p = 0; cudaGetSymbolAddress(&p, sym); return p; }

extern "C" void kernel_launch(void* const* d_in, const int* in_sizes, int n_in,
                              void* d_out, int out_size) {
    const float* item_base = (const float*)d_in[0];
    const float* user_base = (const float*)d_in[1];
    const float* dy_tab    = (const float*)d_in[2];
    const float* Wg        = (const float*)d_in[3];
    const float* bg        = (const float*)d_in[4];
    const float* Wh        = (const float*)d_in[5];
    const float* bh        = (const float*)d_in[6];
    const float* gv        = (const float*)d_in[7];
    const float* ev        = (const float*)d_in[8];
    const int*   rev_i     = (const int*)d_in[9];
    const int*   rev_lat   = (const int*)d_in[10];
    const int*   grows     = (const int*)d_in[11];
    const int*   gcols     = (const int*)d_in[12];
    const int*   erows     = (const int*)d_in[13];
    const int*   ecols     = (const int*)d_in[14];
    float* out = (float*)d_out;

    static cudaStream_t s2 = 0;
    static cudaEvent_t evF = 0, evJ = 0;
    if (!s2) {
        cudaStreamCreateWithFlags(&s2, cudaStreamNonBlocking);
        cudaEventCreateWithFlags(&evF, cudaEventDisableTiming);
        cudaEventCreateWithFlags(&evJ, cudaEventDisableTiming);
        cudaFuncSetAttribute(hgnn_mm, cudaFuncAttributeMaxDynamicSharedMemorySize, HG_SMEM);
        cudaFuncSetAttribute(gate_mm, cudaFuncAttributeMaxDynamicSharedMemorySize, GT_SMEM);
    }

    int* d_gptr = (int*)sym_addr(g_ptrA);
    int* d_gpos = (int*)sym_addr(g_posA);
    int* d_gci  = (int*)sym_addr(g_ci);
    float* d_gcv = (float*)sym_addr(g_cvv);
    int* d_eptr = (int*)sym_addr(e_ptrA);
    int* d_epos = (int*)sym_addr(e_posA);
    int* d_eci  = (int*)sym_addr(e_ci);
    float* d_ecv = (float*)sym_addr(e_cvv);
    __half* d_Yh = (__half*)sym_addr(g_Yh);
    __half* d_Eh = (__half*)sym_addr(g_Eh);
    __half* d_Xs = (__half*)sym_addr(g_Xs);
    int* d_gcnt = (int*)sym_addr(g_cnt);
    int* d_ecnt = (int*)sym_addr(e_cnt);

    dim3 tgrid(GRIDX, TT);

    // fork: CSR build on s2 overlaps the dense prologue
    cudaEventRecord(evF, 0);
    cudaStreamWaitEvent(s2, evF, 0);

    // launch indices (memcpys count): gate_mm lands at 5 for ncu "-s 5 -c 1"
    cudaMemcpyAsync(out, user_base, (size_t)USER_NUM * HD * sizeof(float),
                    cudaMemcpyDeviceToDevice, 0);                                   // 0
    cudaMemcpyAsync(out + (size_t)(USER_NUM + TT * MSUB) * HD, item_base,
                    (size_t)ITEM_NUM * HD * sizeof(float), cudaMemcpyDeviceToDevice, 0); // 1
    prep_w<<<24, 256>>>(Wg, Wh);                                                    // 2
    prep_tables<<<((ITEM_NUM + ITEM_DY_NUM) * 32 + 255) / 256, 256>>>(item_base, dy_tab); // 3
    zero_cnt_kernel<<<(TT * NSUB + 255) / 256, 256, 0, s2>>>();                     // 4
    gate_mm<<<tgrid, 512, GT_SMEM>>>(bg, rev_i, rev_lat);                           // 5 <- profiled
    hist_kernel<<<(TT * NNZG + 255) / 256, 256, 0, s2>>>(grows, d_gcnt, NNZG, NSUB);
    hist_kernel<<<(TT * NNZE + 255) / 256, 256, 0, s2>>>(erows, d_ecnt, NNZE, MSUB);
    scan2_kernel<<<16, 1024, 0, s2>>>();
    scatter_kernel<<<(TT * NNZG + 255) / 256, 256, 0, s2>>>(grows, gcols, gv, d_gpos, d_gci, d_gcv, NNZG, NSUB);
    scatter_kernel<<<(TT * NNZE + 255) / 256, 256, 0, s2>>>(erows, ecols, ev, d_epos, d_eci, d_ecv, NNZE, MSUB);
    cudaEventRecord(evJ, s2);

    hgnn_mm<<<tgrid, 512, HG_SMEM>>>(0);

    // join: SpMM needs CSR
    cudaStreamWaitEvent(0, evJ, 0);

    float* out_item = out + (size_t)(USER_NUM + TT * MSUB + ITEM_NUM) * HD;
    float* out_user = out + (size_t)USER_NUM * HD;

    // layer 0 SpMM: gather g_Yh (fp16), write fp16 g_Xs
    spmm_h<<<(TT * NSUB * 32) / 256, 256>>>(d_gptr, d_gci, d_gcv,
        d_Yh, (long)NSUB * HD, (float*)nullptr, 0, d_Xs,
        bh + 0 * HD, 2 * HD, NSUB, NNZG, 1);
    hgnn_mm<<<tgrid, 512, HG_SMEM>>>(1);
    // layer 1 SpMM: gather g_Yh, write fp32 out_item + fp16 image g_Eh
    spmm_h<<<(TT * NSUB * 32) / 256, 256>>>(d_gptr, d_gci, d_gcv,
        d_Yh, (long)NSUB * HD, out_item, (long)NSUB * HD, d_Eh,
        bh + 1 * HD, 2 * HD, NSUB, NNZG, 1);
    // edge aggregation: gather g_Eh (fp16), write fp32 user area
    spmm_h<<<(TT * MSUB * 32) / 256, 256>>>(d_eptr, d_eci, d_ecv,
        d_Eh, (long)NSUB * HD, out_user, (long)MSUB * HD, (__half*)nullptr,
        (const float*)nullptr, 0, MSUB, NNZE, 0);
}

// round 16
// speedup vs baseline: 1.1873x; 1.0416x over previous
#include <cuda_runtime.h>
#include <cuda_fp16.h>
#include <cstdint>

#define TT 8
#define NSUB 20000
#define MSUB 5000
#define HD 128
#define NNZG 200000
#define NNZE 100000
#define ITEM_NUM 40000
#define USER_NUM 10000
#define ITEM_DY_NUM 60000

#define LDA2 136
#define LDB 136
#define B_BYTES (256 * LDB * 2)       // 69632 (hgnn B: hi+lo)
#define GB_BYTES (128 * LDB * 2)      // 34816 (gate B: hi only)
#define GA_BYTES (64 * LDA2 * 2)      // 17408
#define GT_SMEM (GB_BYTES + 4 * GA_BYTES)  // 104448
#define HG_SMEM (B_BYTES + 2 * GA_BYTES)   // 104448
#define GRIDX 36                      // 36*8=288 CTAs; 2/SM -> single wave
#define GTILES ((NSUB + 63) / 64)     // 313

// ---------------- scratch ---------------------------------------------------
__device__ __align__(16) __half g_Yh[(long)TT * NSUB * HD];
__device__ __align__(16) __half g_Eh[(long)TT * NSUB * HD];
__device__ __align__(16) __half g_Wt[24 * 256 * LDB];
__device__ __align__(16) __half g_items[(long)ITEM_NUM * HD];
__device__ __align__(16) __half g_dys[(long)ITEM_DY_NUM * HD];
__device__ __align__(16) __half g_Xs[(long)TT * NSUB * HD];

__device__ int   g_cnt[TT * NSUB];
__device__ int   g_ptrA[TT * (NSUB + 1)];
__device__ int   g_posA[TT * NSUB];
__device__ int   g_ci[TT * NNZG];
__device__ float g_cvv[TT * NNZG];

__device__ int   e_cnt[TT * MSUB];
__device__ int   e_ptrA[TT * (MSUB + 1)];
__device__ int   e_posA[TT * MSUB];
__device__ int   e_ci[TT * NNZE];
__device__ float e_cvv[TT * NNZE];

// ---------------- helpers ---------------------------------------------------
__device__ __forceinline__ uint32_t smem_u32(const void* p) {
    uint32_t a;
    asm("{ .reg .u64 t; cvta.to.shared.u64 t, %1; cvt.u32.u64 %0, t; }" : "=r"(a) : "l"(p));
    return a;
}
__device__ __forceinline__ void ldsm4(uint32_t* r, uint32_t addr) {
    asm volatile("ldmatrix.sync.aligned.m8n8.x4.shared.b16 {%0,%1,%2,%3}, [%4];"
                 : "=r"(r[0]), "=r"(r[1]), "=r"(r[2]), "=r"(r[3]) : "r"(addr));
}
__device__ __forceinline__ void ldsm4t(uint32_t* r, uint32_t addr) {
    asm volatile("ldmatrix.sync.aligned.m8n8.x4.trans.shared.b16 {%0,%1,%2,%3}, [%4];"
                 : "=r"(r[0]), "=r"(r[1]), "=r"(r[2]), "=r"(r[3]) : "r"(addr));
}
__device__ __forceinline__ void mma16816(float* c, const uint32_t* a, const uint32_t* b) {
    asm volatile("mma.sync.aligned.m16n8k16.row.col.f32.f16.f16.f32 "
                 "{%0,%1,%2,%3}, {%4,%5,%6,%7}, {%8,%9}, {%0,%1,%2,%3};"
                 : "+f"(c[0]), "+f"(c[1]), "+f"(c[2]), "+f"(c[3])
                 : "r"(a[0]), "r"(a[1]), "r"(a[2]), "r"(a[3]), "r"(b[0]), "r"(b[1]));
}
__device__ __forceinline__ void split4h(float4 v, uint2& hi, uint2& lo) {
    __half h[4], l[4];
    float x[4] = {v.x, v.y, v.z, v.w};
#pragma unroll
    for (int j = 0; j < 4; j++) {
        h[j] = __float2half(x[j]);
        l[j] = __float2half(x[j] - __half2float(h[j]));
    }
    hi = *(uint2*)h; lo = *(uint2*)l;
}
#define CP16(dst, src) asm volatile("cp.async.cg.shared.global [%0], [%1], 16;" :: "r"(dst), "l"(src))
#define CP_COMMIT()    asm volatile("cp.async.commit_group;" ::: "memory")
#define CP_WAIT1()     asm volatile("cp.async.wait_group 1;" ::: "memory")

// ---------------- CSR build --------------------------------------------------
__global__ void zero_cnt_kernel() {
    int i = blockIdx.x * blockDim.x + threadIdx.x;
    if (i < TT * NSUB) g_cnt[i] = 0;
    if (i < TT * MSUB) e_cnt[i] = 0;
}

__global__ void hist_kernel(const int* __restrict__ rows, int* __restrict__ cnt,
                            int nnz, int nrows) {
    int i = blockIdx.x * blockDim.x + threadIdx.x;
    if (i >= TT * nnz) return;
    int t = i / nnz;
    atomicAdd(&cnt[t * nrows + rows[i]], 1);
}

__global__ __launch_bounds__(1024) void scan2_kernel() {
    int b = blockIdx.x;
    const int* cnt; int* ptr; int* pos; int n;
    if (b < TT) { cnt = g_cnt + b * NSUB; ptr = g_ptrA + b * (NSUB + 1); pos = g_posA + b * NSUB; n = NSUB; }
    else { int t = b - TT; cnt = e_cnt + t * MSUB; ptr = e_ptrA + t * (MSUB + 1); pos = e_posA + t * MSUB; n = MSUB; }
    __shared__ int wsum[32];
    __shared__ int s_carry;
    int tid = threadIdx.x, lane = tid & 31, wp = tid >> 5;
    if (tid == 0) s_carry = 0;
    __syncthreads();
    for (int base = 0; base < n; base += 8192) {
        int i0 = base + tid * 8;
        int v[8]; int sum = 0;
#pragma unroll
        for (int j = 0; j < 8; j++) { v[j] = (i0 + j < n) ? cnt[i0 + j] : 0; sum += v[j]; }
        int s = sum;
#pragma unroll
        for (int o = 1; o < 32; o <<= 1) { int u = __shfl_up_sync(0xffffffffu, s, o); if (lane >= o) s += u; }
        if (lane == 31) wsum[wp] = s;
        __syncthreads();
        if (wp == 0) {
            int t2 = wsum[lane];
            int ss = t2;
#pragma unroll
            for (int o = 1; o < 32; o <<= 1) { int u = __shfl_up_sync(0xffffffffu, ss, o); if (lane >= o) ss += u; }
            wsum[lane] = ss - t2;
        }
        __syncthreads();
        int run = s_carry + wsum[wp] + s - sum;
#pragma unroll
        for (int j = 0; j < 8; j++) {
            if (i0 + j < n) { ptr[i0 + j] = run; pos[i0 + j] = run; }
            run += v[j];
        }
        __syncthreads();
        if (tid == 1023) s_carry = run;
        __syncthreads();
    }
    if (tid == 0) ptr[n] = s_carry;
}

__global__ void scatter_kernel(const int* __restrict__ rows, const int* __restrict__ cols,
                               const float* __restrict__ vals, int* __restrict__ pos,
                               int* __restrict__ ci, float* __restrict__ cv,
                               int nnz, int nrows) {
    int i = blockIdx.x * blockDim.x + threadIdx.x;
    if (i >= TT * nnz) return;
    int t = i / nnz;
    int r = rows[i];
    int p = atomicAdd(&pos[t * nrows + r], 1);
    ci[(long)t * nnz + p] = cols[i];
    cv[(long)t * nnz + p] = vals[i];
}

// ---------------- SpMM: fp16 row gather -------------------------------------
__global__ void spmm_h(const int* __restrict__ ptr, const int* __restrict__ ci,
                       const float* __restrict__ cv,
                       const __half* __restrict__ xh, long xts,
                       float* __restrict__ yb, long yts,
                       __half* __restrict__ ys_hi,
                       const float* __restrict__ bias, int bstride,
                       int rows_per_t, int nnz, int do_relu) {
    int w = (blockIdx.x * blockDim.x + threadIdx.x) >> 5;
    int lane = threadIdx.x & 31;
    if (w >= TT * rows_per_t) return;
    int t = w / rows_per_t;
    int r = w - t * rows_per_t;
    const int* pp = ptr + t * (rows_per_t + 1);
    int jb = pp[r], je = pp[r + 1];
    const uint2* x2 = (const uint2*)(xh + (long)t * xts);
    const int*   cit = ci + (long)t * nnz;
    const float* cvt = cv + (long)t * nnz;
    float4 acc = make_float4(0.f, 0.f, 0.f, 0.f);
    float vsum = 0.f;
    int j = jb;
    for (; j + 4 <= je; j += 4) {
        int c0 = __ldg(cit + j),     c1 = __ldg(cit + j + 1);
        int c2 = __ldg(cit + j + 2), c3 = __ldg(cit + j + 3);
        float v0 = __ldg(cvt + j),     v1 = __ldg(cvt + j + 1);
        float v2 = __ldg(cvt + j + 2), v3 = __ldg(cvt + j + 3);
        uint2 u0 = x2[(long)c0 * 32 + lane];
        uint2 u1 = x2[(long)c1 * 32 + lane];
        uint2 u2 = x2[(long)c2 * 32 + lane];
        uint2 u3 = x2[(long)c3 * 32 + lane];
        vsum += v0 + v1 + v2 + v3;
        float2 a0 = __half22float2(*(__half2*)&u0.x), b0 = __half22float2(*(__half2*)&u0.y);
        float2 a1 = __half22float2(*(__half2*)&u1.x), b1 = __half22float2(*(__half2*)&u1.y);
        float2 a2 = __half22float2(*(__half2*)&u2.x), b2 = __half22float2(*(__half2*)&u2.y);
        float2 a3 = __half22float2(*(__half2*)&u3.x), b3 = __half22float2(*(__half2*)&u3.y);
        acc.x += v0 * a0.x + v1 * a1.x + v2 * a2.x + v3 * a3.x;
        acc.y += v0 * a0.y + v1 * a1.y + v2 * a2.y + v3 * a3.y;
        acc.z += v0 * b0.x + v1 * b1.x + v2 * b2.x + v3 * b3.x;
        acc.w += v0 * b0.y + v1 * b1.y + v2 * b2.y + v3 * b3.y;
    }
    for (; j < je; j++) {
        int   c0 = __ldg(cit + j);
        float v0 = __ldg(cvt + j);
        uint2 u0 = x2[(long)c0 * 32 + lane];
        float2 a0 = __half22float2(*(__half2*)&u0.x), b0 = __half22float2(*(__half2*)&u0.y);
        vsum += v0;
        acc.x += v0 * a0.x; acc.y += v0 * a0.y;
        acc.z += v0 * b0.x; acc.w += v0 * b0.y;
    }
    if (bias) {
        float4 bv = ((const float4*)(bias + (long)t * bstride))[lane];
        acc.x += vsum * bv.x; acc.y += vsum * bv.y; acc.z += vsum * bv.z; acc.w += vsum * bv.w;
    }
    if (do_relu) {
        acc.x = fmaxf(acc.x, 0.f); acc.y = fmaxf(acc.y, 0.f);
        acc.z = fmaxf(acc.z, 0.f); acc.w = fmaxf(acc.w, 0.f);
    }
    if (ys_hi) {
        uint2 hp;
        *(__half2*)&hp.x = __floats2half2_rn(acc.x, acc.y);
        *(__half2*)&hp.y = __floats2half2_rn(acc.z, acc.w);
        ((uint2*)(ys_hi + ((long)t * rows_per_t + r) * HD))[lane] = hp;
    }
    if (yb)
        ((float4*)(yb + (long)t * yts))[r * 32 + lane] = acc;
}

// ---------------- prep_w ----------------------------------------------------
__global__ __launch_bounds__(256) void prep_w(const float* __restrict__ Wg,
                                              const float* __restrict__ Wh) {
    int b = blockIdx.x, t = b / 3, s = b % 3;
    int tid = threadIdx.x;
    const float* W = (s == 0) ? Wg + (long)t * 16384 : Wh + ((long)t * 2 + (s - 1)) * 16384;
    __half* dst = g_Wt + (long)b * 256 * LDB;
    const float4* w4 = (const float4*)W;
    for (int i = tid; i < 4096; i += 256) {
        int k = i >> 5, c4 = (i & 31) * 4;
        uint2 hi, lo; split4h(w4[i], hi, lo);
        *(uint2*)(dst + k * LDB + c4) = hi;
        *(uint2*)(dst + (k + 128) * LDB + c4) = lo;
    }
}

// ---------------- prep_tables -----------------------------------------------
__global__ __launch_bounds__(256) void prep_tables(const float* __restrict__ ib,
                                                   const float* __restrict__ dt) {
    long i = (long)blockIdx.x * blockDim.x + threadIdx.x;
    const long NI = (long)ITEM_NUM * 32;
    const long ND = (long)ITEM_DY_NUM * 32;
    if (i < NI) {
        float4 v = ((const float4*)ib)[i];
        uint2 hp;
        *(__half2*)&hp.x = __floats2half2_rn(v.x, v.y);
        *(__half2*)&hp.y = __floats2half2_rn(v.z, v.w);
        ((uint2*)g_items)[i] = hp;
    } else if (i < NI + ND) {
        long j = i - NI;
        float4 v = ((const float4*)dt)[j];
        uint2 hp;
        *(__half2*)&hp.x = __floats2half2_rn(v.x, v.y);
        *(__half2*)&hp.y = __floats2half2_rn(v.z, v.w);
        ((uint2*)g_dys)[j] = hp;
    }
}

// ---------------- gate: fp16 tiles, 1-term logits, M=64, 2 CTAs/SM ----------
__global__ __launch_bounds__(512, 2) void gate_mm(
    const float* __restrict__ bg,
    const int* __restrict__ rev_i, const int* __restrict__ rev_lat) {
    extern __shared__ char sm[];
    uint32_t smbU = smem_u32(sm);
    int t = blockIdx.y;
    int tid = threadIdx.x, lane = tid & 31, wid = tid >> 5;
    int wm = wid & 1, wn = wid >> 1;   // 2 x 8 warps (M=64, N=128)

    {
        const char* bsrc = (const char*)(g_Wt + (long)(t * 3) * 256 * LDB);
        for (int q = tid; q < GB_BYTES / 16; q += 512)
            CP16(smbU + q * 16, bsrc + q * 16);
    }
    auto fillA = [&](int p, int tile) {
        int rbase = tile * 64;
        uint32_t aBase = smbU + GB_BYTES + p * 2 * GA_BYTES;
        for (int i = tid; i < 2048; i += 512) {
            int which = i >> 10;
            int r = (i & 1023) >> 4, ch = i & 15;
            int row = rbase + r; if (row >= NSUB) row = NSUB - 1;
            int gidx = which ? __ldg(rev_lat + t * NSUB + row) : __ldg(rev_i + t * NSUB + row);
            const char* src = (const char*)((which ? g_dys : g_items) + (long)gidx * HD) + ch * 16;
            CP16(aBase + which * GA_BYTES + r * (LDA2 * 2) + ch * 16, src);
        }
    };

    int i0 = blockIdx.x;
    fillA(0, i0);
    CP_COMMIT();

    int buf = 0;
    for (int i = i0; i < GTILES; i += GRIDX) {
        int nxt = i + GRIDX;
        if (nxt < GTILES) fillA(buf ^ 1, nxt);
        CP_COMMIT();
        CP_WAIT1();
        __syncthreads();

        float acc0[2][2][4], acc1[2][2][4];
#pragma unroll
        for (int mi = 0; mi < 2; mi++)
#pragma unroll
            for (int nj = 0; nj < 2; nj++)
#pragma unroll
                for (int q = 0; q < 4; q++) { acc0[mi][nj][q] = 0.f; acc1[mi][nj][q] = 0.f; }

        uint32_t a0Base = smbU + GB_BYTES + buf * 2 * GA_BYTES;
        uint32_t a1Base = a0Base + GA_BYTES;
#pragma unroll
        for (int ks = 0; ks < 8; ks++) {
            int k = ks * 16;
            uint32_t a0h[2][4], a1h[2][4], bb[4];
#pragma unroll
            for (int mi = 0; mi < 2; mi++) {
                uint32_t off = ((wm * 32 + mi * 16 + (lane & 15)) * LDA2 + k + (lane >> 4) * 8) * 2;
                ldsm4(a0h[mi], a0Base + off);
                ldsm4(a1h[mi], a1Base + off);
            }
            ldsm4t(bb, smbU + ((k + (lane & 15)) * LDB + wn * 16 + (lane >> 4) * 8) * 2);
#pragma unroll
            for (int mi = 0; mi < 2; mi++)
#pragma unroll
                for (int nj = 0; nj < 2; nj++) {
                    mma16816(acc0[mi][nj], a0h[mi], &bb[nj * 2]);
                    mma16816(acc1[mi][nj], a1h[mi], &bb[nj * 2]);
                }
        }

        {   // epilogue
            const __half* A0h = (const __half*)(sm + GB_BYTES + buf * 2 * GA_BYTES);
            const __half* A1h = A0h + GA_BYTES / 2;
            int rbase = i * 64;
#pragma unroll
            for (int mi = 0; mi < 2; mi++)
#pragma unroll
                for (int nj = 0; nj < 2; nj++)
#pragma unroll
                    for (int h = 0; h < 2; h++) {
                        int r = wm * 32 + mi * 16 + (lane >> 2) + h * 8;
                        int grow = rbase + r;
                        if (grow >= NSUB) continue;
                        int col = wn * 16 + nj * 8 + (lane & 3) * 2;
                        float pa0 = acc0[mi][nj][h * 2], pa1 = acc0[mi][nj][h * 2 + 1];
                        float pb0 = acc1[mi][nj][h * 2], pb1 = acc1[mi][nj][h * 2 + 1];
                        float2 x0 = __half22float2(*(const __half2*)(A0h + r * LDA2 + col));
                        float2 x1 = __half22float2(*(const __half2*)(A1h + r * LDA2 + col));
                        float bv0 = __ldg(bg + t * HD + col), bv1 = __ldg(bg + t * HD + col + 1);
                        float s0a = __fdividef(1.f, 1.f + __expf(-(pa0 + bv0)));
                        float s0b = __fdividef(1.f, 1.f + __expf(-(pb0 + bv0)));
                        float s1a = __fdividef(1.f, 1.f + __expf(-(pa1 + bv1)));
                        float s1b = __fdividef(1.f, 1.f + __expf(-(pb1 + bv1)));
                        float ox = x0.x * s0a + x1.x * s0b;
                        float oy = x0.y * s1a + x1.y * s1b;
                        __half* yr = g_Xs + ((long)t * NSUB + grow) * HD;
                        *(__half2*)(yr + col) = __floats2half2_rn(ox, oy);
                    }
        }
        __syncthreads();
        buf ^= 1;
    }
}

// ---------------- hgnn: 2-term, fp16 A, M=64, 2 CTAs/SM ---------------------
__global__ __launch_bounds__(512, 2) void hgnn_mm(int l) {
    extern __shared__ char sm[];
    uint32_t smbU = smem_u32(sm);
    int t = blockIdx.y;
    int tid = threadIdx.x, lane = tid & 31, wid = tid >> 5;
    int wm = wid & 1, wn = wid >> 1;   // 2 x 8 warps (M=64, N=128)

    {
        const char* bsrc = (const char*)(g_Wt + (long)(t * 3 + 1 + l) * 256 * LDB);
        for (int q = tid; q < B_BYTES / 16; q += 512)
            CP16(smbU + q * 16, bsrc + q * 16);
    }
    auto fillA = [&](int p, int tile) {
        int rbase = tile * 64;
        uint32_t aBase = smbU + B_BYTES + p * GA_BYTES;
        const __half* xs = g_Xs + (long)t * NSUB * HD;
        for (int i = tid; i < 1024; i += 512) {
            int r = i >> 4, ch = i & 15;
            int row = rbase + r; if (row >= NSUB) row = 0;
            CP16(aBase + r * (LDA2 * 2) + ch * 16, (const char*)(xs + (long)row * HD) + ch * 16);
        }
    };

    int i0 = blockIdx.x;
    fillA(0, i0);
    CP_COMMIT();

    int buf = 0;
    for (int i = i0; i < GTILES; i += GRIDX) {
        int nxt = i + GRIDX;
        if (nxt < GTILES) fillA(buf ^ 1, nxt);
        CP_COMMIT();
        CP_WAIT1();
        __syncthreads();

        float acc[2][2][4];
#pragma unroll
        for (int mi = 0; mi < 2; mi++)
#pragma unroll
            for (int nj = 0; nj < 2; nj++)
#pragma unroll
                for (int q = 0; q < 4; q++) acc[mi][nj][q] = 0.f;

        uint32_t aBase = smbU + B_BYTES + buf * GA_BYTES;
#pragma unroll
        for (int ks = 0; ks < 8; ks++) {
            int k = ks * 16;
            uint32_t ah[2][4], bh[4], bl[4];
#pragma unroll
            for (int mi = 0; mi < 2; mi++)
                ldsm4(ah[mi], aBase + ((wm * 32 + mi * 16 + (lane & 15)) * LDA2 + k + (lane >> 4) * 8) * 2);
            {
                uint32_t off = ((k + (lane & 15)) * LDB + wn * 16 + (lane >> 4) * 8) * 2;
                ldsm4t(bh, smbU + off);
                ldsm4t(bl, smbU + off + 128 * LDB * 2);
            }
#pragma unroll
            for (int mi = 0; mi < 2; mi++)
#pragma unroll
                for (int nj = 0; nj < 2; nj++) {
                    mma16816(acc[mi][nj], ah[mi], &bh[nj * 2]);
                    mma16816(acc[mi][nj], ah[mi], &bl[nj * 2]);
                }
        }

        __half* Yt = g_Yh + (long)t * NSUB * HD;
        int rbase = i * 64;
#pragma unroll
        for (int mi = 0; mi < 2; mi++) {
            int r0 = rbase + wm * 32 + mi * 16 + (lane >> 2);
#pragma unroll
            for (int nj = 0; nj < 2; nj++) {
                int col = wn * 16 + nj * 8 + (lane & 3) * 2;
                if (r0 < NSUB)
                    *(__half2*)(Yt + (long)r0 * HD + col) = __floats2half2_rn(acc[mi][nj][0], acc[mi][nj][1]);
                if (r0 + 8 < NSUB)
                    *(__half2*)(Yt + (long)(r0 + 8) * HD + col) = __floats2half2_rn(acc[mi][nj][2], acc[mi][nj][3]);
            }
        }
        __syncthreads();
        buf ^= 1;
    }
}

// ---------------- host ------------------------------------------------------
static void* sym_addr(const void* sym) { void* p = 0; cudaGetSymbolAddress(&p, sym); return p; }

extern "C" void kernel_launch(void* const* d_in, const int* in_sizes, int n_in,
                              void* d_out, int out_size) {
    const float* item_base = (const float*)d_in[0];
    const float* user_base = (const float*)d_in[1];
    const float* dy_tab    = (const float*)d_in[2];
    const float* Wg        = (const float*)d_in[3];
    const float* bg        = (const float*)d_in[4];
    const float* Wh        = (const float*)d_in[5];
    const float* bh        = (const float*)d_in[6];
    const float* gv        = (const float*)d_in[7];
    const float* ev        = (const float*)d_in[8];
    const int*   rev_i     = (const int*)d_in[9];
    const int*   rev_lat   = (const int*)d_in[10];
    const int*   grows     = (const int*)d_in[11];
    const int*   gcols     = (const int*)d_in[12];
    const int*   erows     = (const int*)d_in[13];
    const int*   ecols     = (const int*)d_in[14];
    float* out = (float*)d_out;

    static cudaStream_t s2 = 0;
    static cudaEvent_t evF = 0, evJ = 0;
    if (!s2) {
        cudaStreamCreateWithFlags(&s2, cudaStreamNonBlocking);
        cudaEventCreateWithFlags(&evF, cudaEventDisableTiming);
        cudaEventCreateWithFlags(&evJ, cudaEventDisableTiming);
        cudaFuncSetAttribute(hgnn_mm, cudaFuncAttributeMaxDynamicSharedMemorySize, HG_SMEM);
        cudaFuncSetAttribute(gate_mm, cudaFuncAttributeMaxDynamicSharedMemorySize, GT_SMEM);
    }

    int* d_gptr = (int*)sym_addr(g_ptrA);
    int* d_gpos = (int*)sym_addr(g_posA);
    int* d_gci  = (int*)sym_addr(g_ci);
    float* d_gcv = (float*)sym_addr(g_cvv);
    int* d_eptr = (int*)sym_addr(e_ptrA);
    int* d_epos = (int*)sym_addr(e_posA);
    int* d_eci  = (int*)sym_addr(e_ci);
    float* d_ecv = (float*)sym_addr(e_cvv);
    __half* d_Yh = (__half*)sym_addr(g_Yh);
    __half* d_Eh = (__half*)sym_addr(g_Eh);
    __half* d_Xs = (__half*)sym_addr(g_Xs);
    int* d_gcnt = (int*)sym_addr(g_cnt);
    int* d_ecnt = (int*)sym_addr(e_cnt);

    dim3 tgrid(GRIDX, TT);

    // fork: CSR build on s2 overlaps the dense prologue
    cudaEventRecord(evF, 0);
    cudaStreamWaitEvent(s2, evF, 0);

    // launch indices (memcpys count): gate_mm lands at 5 for ncu "-s 5 -c 1"
    cudaMemcpyAsync(out, user_base, (size_t)USER_NUM * HD * sizeof(float),
                    cudaMemcpyDeviceToDevice, 0);                                   // 0
    cudaMemcpyAsync(out + (size_t)(USER_NUM + TT * MSUB) * HD, item_base,
                    (size_t)ITEM_NUM * HD * sizeof(float), cudaMemcpyDeviceToDevice, 0); // 1
    prep_w<<<24, 256>>>(Wg, Wh);                                                    // 2
    prep_tables<<<((ITEM_NUM + ITEM_DY_NUM) * 32 + 255) / 256, 256>>>(item_base, dy_tab); // 3
    zero_cnt_kernel<<<(TT * NSUB + 255) / 256, 256, 0, s2>>>();                     // 4
    gate_mm<<<tgrid, 512, GT_SMEM>>>(bg, rev_i, rev_lat);                           // 5 <- profiled
    hist_kernel<<<(TT * NNZG + 255) / 256, 256, 0, s2>>>(grows, d_gcnt, NNZG, NSUB);
    hist_kernel<<<(TT * NNZE + 255) / 256, 256, 0, s2>>>(erows, d_ecnt, NNZE, MSUB);
    scan2_kernel<<<16, 1024, 0, s2>>>();
    scatter_kernel<<<(TT * NNZG + 255) / 256, 256, 0, s2>>>(grows, gcols, gv, d_gpos, d_gci, d_gcv, NNZG, NSUB);
    scatter_kernel<<<(TT * NNZE + 255) / 256, 256, 0, s2>>>(erows, ecols, ev, d_epos, d_eci, d_ecv, NNZE, MSUB);
    cudaEventRecord(evJ, s2);

    hgnn_mm<<<tgrid, 512, HG_SMEM>>>(0);

    // join: SpMM needs CSR
    cudaStreamWaitEvent(0, evJ, 0);

    float* out_item = out + (size_t)(USER_NUM + TT * MSUB + ITEM_NUM) * HD;
    float* out_user = out + (size_t)USER_NUM * HD;

    spmm_h<<<(TT * NSUB * 32) / 256, 256>>>(d_gptr, d_gci, d_gcv,
        d_Yh, (long)NSUB * HD, (float*)nullptr, 0, d_Xs,
        bh + 0 * HD, 2 * HD, NSUB, NNZG, 1);
    hgnn_mm<<<tgrid, 512, HG_SMEM>>>(1);
    spmm_h<<<(TT * NSUB * 32) / 256, 256>>>(d_gptr, d_gci, d_gcv,
        d_Yh, (long)NSUB * HD, out_item, (long)NSUB * HD, d_Eh,
        bh + 1 * HD, 2 * HD, NSUB, NNZG, 1);
    spmm_h<<<(TT * MSUB * 32) / 256, 256>>>(d_eptr, d_eci, d_ecv,
        d_Eh, (long)NSUB * HD, out_user, (long)MSUB * HD, (__half*)nullptr,
        (const float*)nullptr, 0, MSUB, NNZE, 0);
}

// round 17
// speedup vs baseline: 1.1909x; 1.0030x over previous
#include <cuda_runtime.h>
#include <cuda_fp16.h>
#include <cstdint>

#define TT 8
#define HTT 4                         // t-half size
#define NSUB 20000
#define MSUB 5000
#define HD 128
#define NNZG 200000
#define NNZE 100000
#define ITEM_NUM 40000
#define USER_NUM 10000
#define ITEM_DY_NUM 60000

#define LDA2 136
#define LDB 136
#define B_BYTES (256 * LDB * 2)       // 69632
#define GB_BYTES (128 * LDB * 2)      // 34816
#define GA_BYTES (64 * LDA2 * 2)      // 17408
#define GT_SMEM (GB_BYTES + 4 * GA_BYTES)  // 104448
#define HG_SMEM (B_BYTES + 2 * GA_BYTES)   // 104448
#define GRIDX 36
#define GTILES ((NSUB + 63) / 64)     // 313

// ---------------- scratch ---------------------------------------------------
__device__ __align__(16) __half g_Yh[(long)TT * NSUB * HD];
__device__ __align__(16) __half g_Eh[(long)TT * NSUB * HD];
__device__ __align__(16) __half g_Wt[24 * 256 * LDB];
__device__ __align__(16) __half g_items[(long)ITEM_NUM * HD];
__device__ __align__(16) __half g_dys[(long)ITEM_DY_NUM * HD];
__device__ __align__(16) __half g_Xs[(long)TT * NSUB * HD];

__device__ int   g_cnt[TT * NSUB];
__device__ int   g_ptrA[TT * (NSUB + 1)];
__device__ int   g_posA[TT * NSUB];
__device__ int   g_ci[TT * NNZG];
__device__ float g_cvv[TT * NNZG];

__device__ int   e_cnt[TT * MSUB];
__device__ int   e_ptrA[TT * (MSUB + 1)];
__device__ int   e_posA[TT * MSUB];
__device__ int   e_ci[TT * NNZE];
__device__ float e_cvv[TT * NNZE];

// ---------------- helpers ---------------------------------------------------
__device__ __forceinline__ uint32_t smem_u32(const void* p) {
    uint32_t a;
    asm("{ .reg .u64 t; cvta.to.shared.u64 t, %1; cvt.u32.u64 %0, t; }" : "=r"(a) : "l"(p));
    return a;
}
__device__ __forceinline__ void ldsm4(uint32_t* r, uint32_t addr) {
    asm volatile("ldmatrix.sync.aligned.m8n8.x4.shared.b16 {%0,%1,%2,%3}, [%4];"
                 : "=r"(r[0]), "=r"(r[1]), "=r"(r[2]), "=r"(r[3]) : "r"(addr));
}
__device__ __forceinline__ void ldsm4t(uint32_t* r, uint32_t addr) {
    asm volatile("ldmatrix.sync.aligned.m8n8.x4.trans.shared.b16 {%0,%1,%2,%3}, [%4];"
                 : "=r"(r[0]), "=r"(r[1]), "=r"(r[2]), "=r"(r[3]) : "r"(addr));
}
__device__ __forceinline__ void mma16816(float* c, const uint32_t* a, const uint32_t* b) {
    asm volatile("mma.sync.aligned.m16n8k16.row.col.f32.f16.f16.f32 "
                 "{%0,%1,%2,%3}, {%4,%5,%6,%7}, {%8,%9}, {%0,%1,%2,%3};"
                 : "+f"(c[0]), "+f"(c[1]), "+f"(c[2]), "+f"(c[3])
                 : "r"(a[0]), "r"(a[1]), "r"(a[2]), "r"(a[3]), "r"(b[0]), "r"(b[1]));
}
__device__ __forceinline__ void split4h(float4 v, uint2& hi, uint2& lo) {
    __half h[4], l[4];
    float x[4] = {v.x, v.y, v.z, v.w};
#pragma unroll
    for (int j = 0; j < 4; j++) {
        h[j] = __float2half(x[j]);
        l[j] = __float2half(x[j] - __half2float(h[j]));
    }
    hi = *(uint2*)h; lo = *(uint2*)l;
}
#define CP16(dst, src) asm volatile("cp.async.cg.shared.global [%0], [%1], 16;" :: "r"(dst), "l"(src))
#define CP_COMMIT()    asm volatile("cp.async.commit_group;" ::: "memory")
#define CP_WAIT1()     asm volatile("cp.async.wait_group 1;" ::: "memory")

// ---------------- CSR build --------------------------------------------------
__global__ void zero_cnt_kernel() {
    int i = blockIdx.x * blockDim.x + threadIdx.x;
    if (i < TT * NSUB) g_cnt[i] = 0;
    if (i < TT * MSUB) e_cnt[i] = 0;
}

__global__ void hist_kernel(const int* __restrict__ rows, int* __restrict__ cnt,
                            int nnz, int nrows) {
    int i = blockIdx.x * blockDim.x + threadIdx.x;
    if (i >= TT * nnz) return;
    int t = i / nnz;
    atomicAdd(&cnt[t * nrows + rows[i]], 1);
}

__global__ __launch_bounds__(1024) void scan2_kernel() {
    int b = blockIdx.x;
    const int* cnt; int* ptr; int* pos; int n;
    if (b < TT) { cnt = g_cnt + b * NSUB; ptr = g_ptrA + b * (NSUB + 1); pos = g_posA + b * NSUB; n = NSUB; }
    else { int t = b - TT; cnt = e_cnt + t * MSUB; ptr = e_ptrA + t * (MSUB + 1); pos = e_posA + t * MSUB; n = MSUB; }
    __shared__ int wsum[32];
    __shared__ int s_carry;
    int tid = threadIdx.x, lane = tid & 31, wp = tid >> 5;
    if (tid == 0) s_carry = 0;
    __syncthreads();
    for (int base = 0; base < n; base += 8192) {
        int i0 = base + tid * 8;
        int v[8]; int sum = 0;
#pragma unroll
        for (int j = 0; j < 8; j++) { v[j] = (i0 + j < n) ? cnt[i0 + j] : 0; sum += v[j]; }
        int s = sum;
#pragma unroll
        for (int o = 1; o < 32; o <<= 1) { int u = __shfl_up_sync(0xffffffffu, s, o); if (lane >= o) s += u; }
        if (lane == 31) wsum[wp] = s;
        __syncthreads();
        if (wp == 0) {
            int t2 = wsum[lane];
            int ss = t2;
#pragma unroll
            for (int o = 1; o < 32; o <<= 1) { int u = __shfl_up_sync(0xffffffffu, ss, o); if (lane >= o) ss += u; }
            wsum[lane] = ss - t2;
        }
        __syncthreads();
        int run = s_carry + wsum[wp] + s - sum;
#pragma unroll
        for (int j = 0; j < 8; j++) {
            if (i0 + j < n) { ptr[i0 + j] = run; pos[i0 + j] = run; }
            run += v[j];
        }
        __syncthreads();
        if (tid == 1023) s_carry = run;
        __syncthreads();
    }
    if (tid == 0) ptr[n] = s_carry;
}

__global__ void scatter_kernel(const int* __restrict__ rows, const int* __restrict__ cols,
                               const float* __restrict__ vals, int* __restrict__ pos,
                               int* __restrict__ ci, float* __restrict__ cv,
                               int nnz, int nrows) {
    int i = blockIdx.x * blockDim.x + threadIdx.x;
    if (i >= TT * nnz) return;
    int t = i / nnz;
    int r = rows[i];
    int p = atomicAdd(&pos[t * nrows + r], 1);
    ci[(long)t * nnz + p] = cols[i];
    cv[(long)t * nnz + p] = vals[i];
}

// ---------------- SpMM: fp16 row gather, half-t batch -----------------------
__global__ void spmm_h(const int* __restrict__ ptr, const int* __restrict__ ci,
                       const float* __restrict__ cv,
                       const __half* __restrict__ xh, long xts,
                       float* __restrict__ yb, long yts,
                       __half* __restrict__ ys_hi,
                       const float* __restrict__ bias, int bstride,
                       int rows_per_t, int nnz, int do_relu, int t0) {
    int w = (blockIdx.x * blockDim.x + threadIdx.x) >> 5;
    int lane = threadIdx.x & 31;
    if (w >= HTT * rows_per_t) return;
    int t = t0 + w / rows_per_t;
    int r = w - (t - t0) * rows_per_t;
    const int* pp = ptr + t * (rows_per_t + 1);
    int jb = pp[r], je = pp[r + 1];
    const uint2* x2 = (const uint2*)(xh + (long)t * xts);
    const int*   cit = ci + (long)t * nnz;
    const float* cvt = cv + (long)t * nnz;
    float4 acc = make_float4(0.f, 0.f, 0.f, 0.f);
    float vsum = 0.f;
    int j = jb;
    for (; j + 4 <= je; j += 4) {
        int c0 = __ldg(cit + j),     c1 = __ldg(cit + j + 1);
        int c2 = __ldg(cit + j + 2), c3 = __ldg(cit + j + 3);
        float v0 = __ldg(cvt + j),     v1 = __ldg(cvt + j + 1);
        float v2 = __ldg(cvt + j + 2), v3 = __ldg(cvt + j + 3);
        uint2 u0 = x2[(long)c0 * 32 + lane];
        uint2 u1 = x2[(long)c1 * 32 + lane];
        uint2 u2 = x2[(long)c2 * 32 + lane];
        uint2 u3 = x2[(long)c3 * 32 + lane];
        vsum += v0 + v1 + v2 + v3;
        float2 a0 = __half22float2(*(__half2*)&u0.x), b0 = __half22float2(*(__half2*)&u0.y);
        float2 a1 = __half22float2(*(__half2*)&u1.x), b1 = __half22float2(*(__half2*)&u1.y);
        float2 a2 = __half22float2(*(__half2*)&u2.x), b2 = __half22float2(*(__half2*)&u2.y);
        float2 a3 = __half22float2(*(__half2*)&u3.x), b3 = __half22float2(*(__half2*)&u3.y);
        acc.x += v0 * a0.x + v1 * a1.x + v2 * a2.x + v3 * a3.x;
        acc.y += v0 * a0.y + v1 * a1.y + v2 * a2.y + v3 * a3.y;
        acc.z += v0 * b0.x + v1 * b1.x + v2 * b2.x + v3 * b3.x;
        acc.w += v0 * b0.y + v1 * b1.y + v2 * b2.y + v3 * b3.y;
    }
    for (; j < je; j++) {
        int   c0 = __ldg(cit + j);
        float v0 = __ldg(cvt + j);
        uint2 u0 = x2[(long)c0 * 32 + lane];
        float2 a0 = __half22float2(*(__half2*)&u0.x), b0 = __half22float2(*(__half2*)&u0.y);
        vsum += v0;
        acc.x += v0 * a0.x; acc.y += v0 * a0.y;
        acc.z += v0 * b0.x; acc.w += v0 * b0.y;
    }
    if (bias) {
        float4 bv = ((const float4*)(bias + (long)t * bstride))[lane];
        acc.x += vsum * bv.x; acc.y += vsum * bv.y; acc.z += vsum * bv.z; acc.w += vsum * bv.w;
    }
    if (do_relu) {
        acc.x = fmaxf(acc.x, 0.f); acc.y = fmaxf(acc.y, 0.f);
        acc.z = fmaxf(acc.z, 0.f); acc.w = fmaxf(acc.w, 0.f);
    }
    if (ys_hi) {
        uint2 hp;
        *(__half2*)&hp.x = __floats2half2_rn(acc.x, acc.y);
        *(__half2*)&hp.y = __floats2half2_rn(acc.z, acc.w);
        ((uint2*)(ys_hi + ((long)t * rows_per_t + r) * HD))[lane] = hp;
    }
    if (yb)
        ((float4*)(yb + (long)t * yts))[r * 32 + lane] = acc;
}

// ---------------- prep_w ----------------------------------------------------
__global__ __launch_bounds__(256) void prep_w(const float* __restrict__ Wg,
                                              const float* __restrict__ Wh) {
    int b = blockIdx.x, t = b / 3, s = b % 3;
    int tid = threadIdx.x;
    const float* W = (s == 0) ? Wg + (long)t * 16384 : Wh + ((long)t * 2 + (s - 1)) * 16384;
    __half* dst = g_Wt + (long)b * 256 * LDB;
    const float4* w4 = (const float4*)W;
    for (int i = tid; i < 4096; i += 256) {
        int k = i >> 5, c4 = (i & 31) * 4;
        uint2 hi, lo; split4h(w4[i], hi, lo);
        *(uint2*)(dst + k * LDB + c4) = hi;
        *(uint2*)(dst + (k + 128) * LDB + c4) = lo;
    }
}

// ---------------- prep_tables -----------------------------------------------
__global__ __launch_bounds__(256) void prep_tables(const float* __restrict__ ib,
                                                   const float* __restrict__ dt) {
    long i = (long)blockIdx.x * blockDim.x + threadIdx.x;
    const long NI = (long)ITEM_NUM * 32;
    const long ND = (long)ITEM_DY_NUM * 32;
    if (i < NI) {
        float4 v = ((const float4*)ib)[i];
        uint2 hp;
        *(__half2*)&hp.x = __floats2half2_rn(v.x, v.y);
        *(__half2*)&hp.y = __floats2half2_rn(v.z, v.w);
        ((uint2*)g_items)[i] = hp;
    } else if (i < NI + ND) {
        long j = i - NI;
        float4 v = ((const float4*)dt)[j];
        uint2 hp;
        *(__half2*)&hp.x = __floats2half2_rn(v.x, v.y);
        *(__half2*)&hp.y = __floats2half2_rn(v.z, v.w);
        ((uint2*)g_dys)[j] = hp;
    }
}

// ---------------- gate: fp16 tiles, 1-term logits, M=64, half-t -------------
__global__ __launch_bounds__(512, 2) void gate_mm(
    const float* __restrict__ bg,
    const int* __restrict__ rev_i, const int* __restrict__ rev_lat, int t0) {
    extern __shared__ char sm[];
    uint32_t smbU = smem_u32(sm);
    int t = blockIdx.y + t0;
    int tid = threadIdx.x, lane = tid & 31, wid = tid >> 5;
    int wm = wid & 1, wn = wid >> 1;

    {
        const char* bsrc = (const char*)(g_Wt + (long)(t * 3) * 256 * LDB);
        for (int q = tid; q < GB_BYTES / 16; q += 512)
            CP16(smbU + q * 16, bsrc + q * 16);
    }
    auto fillA = [&](int p, int tile) {
        int rbase = tile * 64;
        uint32_t aBase = smbU + GB_BYTES + p * 2 * GA_BYTES;
        for (int i = tid; i < 2048; i += 512) {
            int which = i >> 10;
            int r = (i & 1023) >> 4, ch = i & 15;
            int row = rbase + r; if (row >= NSUB) row = NSUB - 1;
            int gidx = which ? __ldg(rev_lat + t * NSUB + row) : __ldg(rev_i + t * NSUB + row);
            const char* src = (const char*)((which ? g_dys : g_items) + (long)gidx * HD) + ch * 16;
            CP16(aBase + which * GA_BYTES + r * (LDA2 * 2) + ch * 16, src);
        }
    };

    int i0 = blockIdx.x;
    fillA(0, i0);
    CP_COMMIT();

    int buf = 0;
    for (int i = i0; i < GTILES; i += GRIDX) {
        int nxt = i + GRIDX;
        if (nxt < GTILES) fillA(buf ^ 1, nxt);
        CP_COMMIT();
        CP_WAIT1();
        __syncthreads();

        float acc0[2][2][4], acc1[2][2][4];
#pragma unroll
        for (int mi = 0; mi < 2; mi++)
#pragma unroll
            for (int nj = 0; nj < 2; nj++)
#pragma unroll
                for (int q = 0; q < 4; q++) { acc0[mi][nj][q] = 0.f; acc1[mi][nj][q] = 0.f; }

        uint32_t a0Base = smbU + GB_BYTES + buf * 2 * GA_BYTES;
        uint32_t a1Base = a0Base + GA_BYTES;
#pragma unroll
        for (int ks = 0; ks < 8; ks++) {
            int k = ks * 16;
            uint32_t a0h[2][4], a1h[2][4], bb[4];
#pragma unroll
            for (int mi = 0; mi < 2; mi++) {
                uint32_t off = ((wm * 32 + mi * 16 + (lane & 15)) * LDA2 + k + (lane >> 4) * 8) * 2;
                ldsm4(a0h[mi], a0Base + off);
                ldsm4(a1h[mi], a1Base + off);
            }
            ldsm4t(bb, smbU + ((k + (lane & 15)) * LDB + wn * 16 + (lane >> 4) * 8) * 2);
#pragma unroll
            for (int mi = 0; mi < 2; mi++)
#pragma unroll
                for (int nj = 0; nj < 2; nj++) {
                    mma16816(acc0[mi][nj], a0h[mi], &bb[nj * 2]);
                    mma16816(acc1[mi][nj], a1h[mi], &bb[nj * 2]);
                }
        }

        {
            const __half* A0h = (const __half*)(sm + GB_BYTES + buf * 2 * GA_BYTES);
            const __half* A1h = A0h + GA_BYTES / 2;
            int rbase = i * 64;
#pragma unroll
            for (int mi = 0; mi < 2; mi++)
#pragma unroll
                for (int nj = 0; nj < 2; nj++)
#pragma unroll
                    for (int h = 0; h < 2; h++) {
                        int r = wm * 32 + mi * 16 + (lane >> 2) + h * 8;
                        int grow = rbase + r;
                        if (grow >= NSUB) continue;
                        int col = wn * 16 + nj * 8 + (lane & 3) * 2;
                        float pa0 = acc0[mi][nj][h * 2], pa1 = acc0[mi][nj][h * 2 + 1];
                        float pb0 = acc1[mi][nj][h * 2], pb1 = acc1[mi][nj][h * 2 + 1];
                        float2 x0 = __half22float2(*(const __half2*)(A0h + r * LDA2 + col));
                        float2 x1 = __half22float2(*(const __half2*)(A1h + r * LDA2 + col));
                        float bv0 = __ldg(bg + t * HD + col), bv1 = __ldg(bg + t * HD + col + 1);
                        float s0a = __fdividef(1.f, 1.f + __expf(-(pa0 + bv0)));
                        float s0b = __fdividef(1.f, 1.f + __expf(-(pb0 + bv0)));
                        float s1a = __fdividef(1.f, 1.f + __expf(-(pa1 + bv1)));
                        float s1b = __fdividef(1.f, 1.f + __expf(-(pb1 + bv1)));
                        float ox = x0.x * s0a + x1.x * s0b;
                        float oy = x0.y * s1a + x1.y * s1b;
                        __half* yr = g_Xs + ((long)t * NSUB + grow) * HD;
                        *(__half2*)(yr + col) = __floats2half2_rn(ox, oy);
                    }
        }
        __syncthreads();
        buf ^= 1;
    }
}

// ---------------- hgnn: 2-term, fp16 A, M=64, half-t ------------------------
__global__ __launch_bounds__(512, 2) void hgnn_mm(int l, int t0) {
    extern __shared__ char sm[];
    uint32_t smbU = smem_u32(sm);
    int t = blockIdx.y + t0;
    int tid = threadIdx.x, lane = tid & 31, wid = tid >> 5;
    int wm = wid & 1, wn = wid >> 1;

    {
        const char* bsrc = (const char*)(g_Wt + (long)(t * 3 + 1 + l) * 256 * LDB);
        for (int q = tid; q < B_BYTES / 16; q += 512)
            CP16(smbU + q * 16, bsrc + q * 16);
    }
    auto fillA = [&](int p, int tile) {
        int rbase = tile * 64;
        uint32_t aBase = smbU + B_BYTES + p * GA_BYTES;
        const __half* xs = g_Xs + (long)t * NSUB * HD;
        for (int i = tid; i < 1024; i += 512) {
            int r = i >> 4, ch = i & 15;
            int row = rbase + r; if (row >= NSUB) row = 0;
            CP16(aBase + r * (LDA2 * 2) + ch * 16, (const char*)(xs + (long)row * HD) + ch * 16);
        }
    };

    int i0 = blockIdx.x;
    fillA(0, i0);
    CP_COMMIT();

    int buf = 0;
    for (int i = i0; i < GTILES; i += GRIDX) {
        int nxt = i + GRIDX;
        if (nxt < GTILES) fillA(buf ^ 1, nxt);
        CP_COMMIT();
        CP_WAIT1();
        __syncthreads();

        float acc[2][2][4];
#pragma unroll
        for (int mi = 0; mi < 2; mi++)
#pragma unroll
            for (int nj = 0; nj < 2; nj++)
#pragma unroll
                for (int q = 0; q < 4; q++) acc[mi][nj][q] = 0.f;

        uint32_t aBase = smbU + B_BYTES + buf * GA_BYTES;
#pragma unroll
        for (int ks = 0; ks < 8; ks++) {
            int k = ks * 16;
            uint32_t ah[2][4], bh[4], bl[4];
#pragma unroll
            for (int mi = 0; mi < 2; mi++)
                ldsm4(ah[mi], aBase + ((wm * 32 + mi * 16 + (lane & 15)) * LDA2 + k + (lane >> 4) * 8) * 2);
            {
                uint32_t off = ((k + (lane & 15)) * LDB + wn * 16 + (lane >> 4) * 8) * 2;
                ldsm4t(bh, smbU + off);
                ldsm4t(bl, smbU + off + 128 * LDB * 2);
            }
#pragma unroll
            for (int mi = 0; mi < 2; mi++)
#pragma unroll
                for (int nj = 0; nj < 2; nj++) {
                    mma16816(acc[mi][nj], ah[mi], &bh[nj * 2]);
                    mma16816(acc[mi][nj], ah[mi], &bl[nj * 2]);
                }
        }

        __half* Yt = g_Yh + (long)t * NSUB * HD;
        int rbase = i * 64;
#pragma unroll
        for (int mi = 0; mi < 2; mi++) {
            int r0 = rbase + wm * 32 + mi * 16 + (lane >> 2);
#pragma unroll
            for (int nj = 0; nj < 2; nj++) {
                int col = wn * 16 + nj * 8 + (lane & 3) * 2;
                if (r0 < NSUB)
                    *(__half2*)(Yt + (long)r0 * HD + col) = __floats2half2_rn(acc[mi][nj][0], acc[mi][nj][1]);
                if (r0 + 8 < NSUB)
                    *(__half2*)(Yt + (long)(r0 + 8) * HD + col) = __floats2half2_rn(acc[mi][nj][2], acc[mi][nj][3]);
            }
        }
        __syncthreads();
        buf ^= 1;
    }
}

// ---------------- host ------------------------------------------------------
static void* sym_addr(const void* sym) { void* p = 0; cudaGetSymbolAddress(&p, sym); return p; }

extern "C" void kernel_launch(void* const* d_in, const int* in_sizes, int n_in,
                              void* d_out, int out_size) {
    const float* item_base = (const float*)d_in[0];
    const float* user_base = (const float*)d_in[1];
    const float* dy_tab    = (const float*)d_in[2];
    const float* Wg        = (const float*)d_in[3];
    const float* bg        = (const float*)d_in[4];
    const float* Wh        = (const float*)d_in[5];
    const float* bh        = (const float*)d_in[6];
    const float* gv        = (const float*)d_in[7];
    const float* ev        = (const float*)d_in[8];
    const int*   rev_i     = (const int*)d_in[9];
    const int*   rev_lat   = (const int*)d_in[10];
    const int*   grows     = (const int*)d_in[11];
    const int*   gcols     = (const int*)d_in[12];
    const int*   erows     = (const int*)d_in[13];
    const int*   ecols     = (const int*)d_in[14];
    float* out = (float*)d_out;

    static cudaStream_t sB = 0, sC = 0;
    static cudaEvent_t evF = 0, evP = 0, evCSR = 0, evB = 0;
    if (!sB) {
        cudaStreamCreateWithFlags(&sB, cudaStreamNonBlocking);
        cudaStreamCreateWithFlags(&sC, cudaStreamNonBlocking);
        cudaEventCreateWithFlags(&evF,   cudaEventDisableTiming);
        cudaEventCreateWithFlags(&evP,   cudaEventDisableTiming);
        cudaEventCreateWithFlags(&evCSR, cudaEventDisableTiming);
        cudaEventCreateWithFlags(&evB,   cudaEventDisableTiming);
        cudaFuncSetAttribute(hgnn_mm, cudaFuncAttributeMaxDynamicSharedMemorySize, HG_SMEM);
        cudaFuncSetAttribute(gate_mm, cudaFuncAttributeMaxDynamicSharedMemorySize, GT_SMEM);
    }

    int* d_gptr = (int*)sym_addr(g_ptrA);
    int* d_gpos = (int*)sym_addr(g_posA);
    int* d_gci  = (int*)sym_addr(g_ci);
    float* d_gcv = (float*)sym_addr(g_cvv);
    int* d_eptr = (int*)sym_addr(e_ptrA);
    int* d_epos = (int*)sym_addr(e_posA);
    int* d_eci  = (int*)sym_addr(e_ci);
    float* d_ecv = (float*)sym_addr(e_cvv);
    __half* d_Yh = (__half*)sym_addr(g_Yh);
    __half* d_Eh = (__half*)sym_addr(g_Eh);
    __half* d_Xs = (__half*)sym_addr(g_Xs);
    int* d_gcnt = (int*)sym_addr(g_cnt);
    int* d_ecnt = (int*)sym_addr(e_cnt);

    float* out_item = out + (size_t)(USER_NUM + TT * MSUB + ITEM_NUM) * HD;
    float* out_user = out + (size_t)USER_NUM * HD;

    dim3 hgrid(GRIDX, HTT);
    const int SPG = (HTT * NSUB * 32) / 256;   // 10000
    const int SPE = (HTT * MSUB * 32) / 256;   // 2500

    // fork CSR stream from origin
    cudaEventRecord(evF, 0);
    cudaStreamWaitEvent(sC, evF, 0);

    // CSR build on sC
    zero_cnt_kernel<<<(TT * NSUB + 255) / 256, 256, 0, sC>>>();
    hist_kernel<<<(TT * NNZG + 255) / 256, 256, 0, sC>>>(grows, d_gcnt, NNZG, NSUB);
    hist_kernel<<<(TT * NNZE + 255) / 256, 256, 0, sC>>>(erows, d_ecnt, NNZE, MSUB);
    scan2_kernel<<<16, 1024, 0, sC>>>();
    scatter_kernel<<<(TT * NNZG + 255) / 256, 256, 0, sC>>>(grows, gcols, gv, d_gpos, d_gci, d_gcv, NNZG, NSUB);
    scatter_kernel<<<(TT * NNZE + 255) / 256, 256, 0, sC>>>(erows, ecols, ev, d_epos, d_eci, d_ecv, NNZE, MSUB);
    cudaEventRecord(evCSR, sC);

    // prologue on origin stream
    cudaMemcpyAsync(out, user_base, (size_t)USER_NUM * HD * sizeof(float),
                    cudaMemcpyDeviceToDevice, 0);
    cudaMemcpyAsync(out + (size_t)(USER_NUM + TT * MSUB) * HD, item_base,
                    (size_t)ITEM_NUM * HD * sizeof(float), cudaMemcpyDeviceToDevice, 0);
    prep_w<<<24, 256>>>(Wg, Wh);
    prep_tables<<<((ITEM_NUM + ITEM_DY_NUM) * 32 + 255) / 256, 256>>>(item_base, dy_tab);
    cudaEventRecord(evP, 0);
    cudaStreamWaitEvent(sB, evP, 0);

    // ---- chain A: t in [0,4) on origin stream ----
    gate_mm<<<hgrid, 512, GT_SMEM, 0>>>(bg, rev_i, rev_lat, 0);
    hgnn_mm<<<hgrid, 512, HG_SMEM, 0>>>(0, 0);
    cudaStreamWaitEvent(0, evCSR, 0);
    spmm_h<<<SPG, 256, 0, 0>>>(d_gptr, d_gci, d_gcv, d_Yh, (long)NSUB * HD,
        (float*)nullptr, 0, d_Xs, bh + 0 * HD, 2 * HD, NSUB, NNZG, 1, 0);
    hgnn_mm<<<hgrid, 512, HG_SMEM, 0>>>(1, 0);
    spmm_h<<<SPG, 256, 0, 0>>>(d_gptr, d_gci, d_gcv, d_Yh, (long)NSUB * HD,
        out_item, (long)NSUB * HD, d_Eh, bh + 1 * HD, 2 * HD, NSUB, NNZG, 1, 0);
    spmm_h<<<SPE, 256, 0, 0>>>(d_eptr, d_eci, d_ecv, d_Eh, (long)NSUB * HD,
        out_user, (long)MSUB * HD, (__half*)nullptr,
        (const float*)nullptr, 0, MSUB, NNZE, 0, 0);

    // ---- chain B: t in [4,8) on sB ----
    gate_mm<<<hgrid, 512, GT_SMEM, sB>>>(bg, rev_i, rev_lat, HTT);
    hgnn_mm<<<hgrid, 512, HG_SMEM, sB>>>(0, HTT);
    cudaStreamWaitEvent(sB, evCSR, 0);
    spmm_h<<<SPG, 256, 0, sB>>>(d_gptr, d_gci, d_gcv, d_Yh, (long)NSUB * HD,
        (float*)nullptr, 0, d_Xs, bh + 0 * HD, 2 * HD, NSUB, NNZG, 1, HTT);
    hgnn_mm<<<hgrid, 512, HG_SMEM, sB>>>(1, HTT);
    spmm_h<<<SPG, 256, 0, sB>>>(d_gptr, d_gci, d_gcv, d_Yh, (long)NSUB * HD,
        out_item, (long)NSUB * HD, d_Eh, bh + 1 * HD, 2 * HD, NSUB, NNZG, 1, HTT);
    spmm_h<<<SPE, 256, 0, sB>>>(d_eptr, d_eci, d_ecv, d_Eh, (long)NSUB * HD,
        out_user, (long)MSUB * HD, (__half*)nullptr,
        (const float*)nullptr, 0, MSUB, NNZE, 0, HTT);
    cudaEventRecord(evB, sB);

    // join chain B back to origin
    cudaStreamWaitEvent(0, evB, 0);
}